// round 1
// baseline (speedup 1.0000x reference)
#include <cuda_runtime.h>
#include <math.h>

// Problem constants
#define Bb 8
#define Tt 4096
#define Cc 512
#define Kt 3
#define Ss 64

// ---------------- scratch (device globals; no runtime allocation) -------------
__device__ float g_T1[(size_t)Bb * Tt * Cc];            // 64 MB
__device__ float g_T2[(size_t)Bb * Tt * Cc];            // 64 MB
__device__ float g_X1[(size_t)Bb * Tt * Cc];            // 64 MB
__device__ float g_W [(size_t)6 * Kt * Cc * Cc];        // normalized conv weights, 18.9 MB
__device__ float g_GB[(size_t)6 * Bb * 2 * Cc];         // style gamma/beta per (block,layer)
__device__ float g_MU[Bb * Cc];
__device__ float g_RS[Bb * Cc];

// ---------------- style MLP: gb[j][b][0:1024] = s @ fcw[j] + fcb[j] -----------
__global__ void style_kernel(const float* __restrict__ s,
                             const float* __restrict__ fc1w, const float* __restrict__ fc1b,
                             const float* __restrict__ fc2w, const float* __restrict__ fc2b,
                             float* __restrict__ gb)
{
    int j = blockIdx.x / Bb;           // 0..5 : 2*i + layer
    int b = blockIdx.x % Bb;
    int i = j >> 1, layer = j & 1;
    const float* w  = (layer ? fc2w : fc1w) + (size_t)i * Ss * 2 * Cc;
    const float* bi = (layer ? fc2b : fc1b) + (size_t)i * 2 * Cc;

    __shared__ float ss[Ss];
    if (threadIdx.x < Ss) ss[threadIdx.x] = s[b * Ss + threadIdx.x];
    __syncthreads();

    for (int n = threadIdx.x; n < 2 * Cc; n += blockDim.x) {
        float acc = bi[n];
#pragma unroll 8
        for (int k = 0; k < Ss; k++) acc += ss[k] * w[(size_t)k * 2 * Cc + n];
        gb[((size_t)j * Bb + b) * 2 * Cc + n] = acc;
    }
}

// ---------------- weight norm: w = g * v / ||v||_(k,ci) per cout ---------------
__global__ void wnorm_kernel(const float* __restrict__ c1v, const float* __restrict__ c1g,
                             const float* __restrict__ c2v, const float* __restrict__ c2g,
                             float* __restrict__ wout)
{
    // grid: 6 * (C/128), block 128; one thread per output channel
    int j  = blockIdx.x / (Cc / 128);
    int co = (blockIdx.x % (Cc / 128)) * 128 + threadIdx.x;
    int i = j >> 1, layer = j & 1;
    const float* v = (layer ? c2v : c1v) + (size_t)i * Kt * Cc * Cc;
    const float* g = (layer ? c2g : c1g) + (size_t)i * Cc;

    float sum = 0.f;
    for (int r = 0; r < Kt * Cc; r++) {
        float t = v[(size_t)r * Cc + co];
        sum += t * t;
    }
    float scale = g[co] * rsqrtf(sum);
    float* wo = wout + (size_t)j * Kt * Cc * Cc;
    for (int r = 0; r < Kt * Cc; r++)
        wo[(size_t)r * Cc + co] = v[(size_t)r * Cc + co] * scale;
}

// ---------------- instance-norm stats over time per (b, c) --------------------
__global__ void stats_kernel(const float* __restrict__ x,
                             float* __restrict__ mu, float* __restrict__ rs)
{
    // grid (C/32, B), block 256 = 32 channels x 8 time-groups
    int b  = blockIdx.y;
    int c0 = blockIdx.x * 32;
    int cl = threadIdx.x & 31;
    int tg = threadIdx.x >> 5;
    const float* base = x + (size_t)b * Tt * Cc + c0 + cl;

    float s = 0.f, s2 = 0.f;
    for (int t = tg; t < Tt; t += 8) {
        float v = base[(size_t)t * Cc];
        s += v; s2 += v * v;
    }
    __shared__ float sh[2][8][32];
    sh[0][tg][cl] = s; sh[1][tg][cl] = s2;
    __syncthreads();
    if (tg == 0) {
        float S = 0.f, S2 = 0.f;
#pragma unroll
        for (int q = 0; q < 8; q++) { S += sh[0][q][cl]; S2 += sh[1][q][cl]; }
        float m   = S * (1.0f / Tt);
        float var = S2 * (1.0f / Tt) - m * m;
        mu[b * Cc + c0 + cl] = m;
        rs[b * Cc + c0 + cl] = rsqrtf(var + 1e-5f);
    }
}

// ---------------- fused adain affine + snake activation -----------------------
__global__ void adain_snake_kernel(const float* __restrict__ x,
                                   const float* __restrict__ mu, const float* __restrict__ rs,
                                   const float* __restrict__ gb,     // [B][1024] (gamma|beta)
                                   const float* __restrict__ alpha,  // [C]
                                   float* __restrict__ out)
{
    size_t idx = (size_t)blockIdx.x * blockDim.x + threadIdx.x;   // float4 index
    size_t e = idx * 4;
    int c = (int)(e & (Cc - 1));
    int b = (int)(e >> 21);                                       // / (T*C) = 2^21

    float4 xv = ((const float4*)x)[idx];
    float4 gv = *(const float4*)(gb + (size_t)b * 2 * Cc + c);
    float4 bv = *(const float4*)(gb + (size_t)b * 2 * Cc + Cc + c);
    float4 mv = *(const float4*)(mu + b * Cc + c);
    float4 rv = *(const float4*)(rs + b * Cc + c);
    float4 av = *(const float4*)(alpha + c);

    float4 o;
    {
        float xn = (xv.x - mv.x) * rv.x;
        float v  = (1.0f + gv.x) * xn + bv.x;
        float sn = sinf(av.x * v);
        o.x = v + (sn * sn) / av.x;
    }
    {
        float xn = (xv.y - mv.y) * rv.y;
        float v  = (1.0f + gv.y) * xn + bv.y;
        float sn = sinf(av.y * v);
        o.y = v + (sn * sn) / av.y;
    }
    {
        float xn = (xv.z - mv.z) * rv.z;
        float v  = (1.0f + gv.z) * xn + bv.z;
        float sn = sinf(av.z * v);
        o.z = v + (sn * sn) / av.z;
    }
    {
        float xn = (xv.w - mv.w) * rv.w;
        float v  = (1.0f + gv.w) * xn + bv.w;
        float sn = sinf(av.w * v);
        o.w = v + (sn * sn) / av.w;
    }
    ((float4*)out)[idx] = o;
}

// ---------------- dilated conv as 3-tap shifted SGEMM -------------------------
// y[m, co] = sum_tap sum_ci in[b, t+(tap-1)*d, ci] * w[tap, ci, co] + bias[co] (+res)
#define BM 128
#define BN 128
#define BK 8
#define TM 8
#define TN 8

__global__ void __launch_bounds__(256, 2)
conv_kernel(const float* __restrict__ in, const float* __restrict__ w,
            const float* __restrict__ bias, const float* __restrict__ res,
            float* __restrict__ out, int dil)
{
    __shared__ float As[BK][BM];
    __shared__ float Bs[BK][BN];

    const int tid = threadIdx.x;
    const int block_m = blockIdx.x * BM;
    const int block_n = blockIdx.y * BN;
    const int tx = tid & 15, ty = tid >> 4;

    // A-load mapping: 128 rows x 8 cols, one float4 per thread
    const int a_row = tid >> 1;
    const int a_col = (tid & 1) * 4;
    // B-load mapping: 8 rows x 128 cols, one float4 per thread
    const int b_row = tid >> 5;
    const int b_col = (tid & 31) * 4;

    const int m  = block_m + a_row;
    const int bb = m >> 12;            // / T
    const int t  = m & (Tt - 1);

    float acc[TM][TN];
#pragma unroll
    for (int i = 0; i < TM; i++)
#pragma unroll
        for (int j = 0; j < TN; j++) acc[i][j] = 0.f;

    for (int tap = 0; tap < Kt; ++tap) {
        const int tp = t + (tap - 1) * dil;
        const bool valid = ((unsigned)tp < (unsigned)Tt);
        const float* a_base = in + ((size_t)bb * Tt + tp) * Cc;
        const float* w_base = w + (size_t)tap * Cc * Cc;

        for (int kk = 0; kk < Cc; kk += BK) {
            float4 av = valid ? *(const float4*)(a_base + kk + a_col)
                              : make_float4(0.f, 0.f, 0.f, 0.f);
            As[a_col + 0][a_row] = av.x;
            As[a_col + 1][a_row] = av.y;
            As[a_col + 2][a_row] = av.z;
            As[a_col + 3][a_row] = av.w;

            *(float4*)&Bs[b_row][b_col] =
                *(const float4*)(w_base + (size_t)(kk + b_row) * Cc + block_n + b_col);
            __syncthreads();

#pragma unroll
            for (int p = 0; p < BK; ++p) {
                float af[TM], bf[TN];
                *(float4*)&af[0] = *(const float4*)&As[p][ty * TM];
                *(float4*)&af[4] = *(const float4*)&As[p][ty * TM + 4];
                *(float4*)&bf[0] = *(const float4*)&Bs[p][tx * TN];
                *(float4*)&bf[4] = *(const float4*)&Bs[p][tx * TN + 4];
#pragma unroll
                for (int i = 0; i < TM; i++)
#pragma unroll
                    for (int j = 0; j < TN; j++)
                        acc[i][j] += af[i] * bf[j];
            }
            __syncthreads();
        }
    }

    // epilogue: bias (+ residual)
    const float* brow = bias + block_n + tx * TN;
#pragma unroll
    for (int i = 0; i < TM; ++i) {
        size_t gm = (size_t)block_m + ty * TM + i;
        float* orow = out + gm * Cc + block_n + tx * TN;
        const float* rrow = res ? res + gm * Cc + block_n + tx * TN : (const float*)0;
#pragma unroll
        for (int j = 0; j < TN; j += 4) {
            float4 v;
            v.x = acc[i][j + 0] + brow[j + 0];
            v.y = acc[i][j + 1] + brow[j + 1];
            v.z = acc[i][j + 2] + brow[j + 2];
            v.w = acc[i][j + 3] + brow[j + 3];
            if (rrow) {
                float4 r = *(const float4*)(rrow + j);
                v.x += r.x; v.y += r.y; v.z += r.z; v.w += r.w;
            }
            *(float4*)(orow + j) = v;
        }
    }
}

// -------------------------------- launch --------------------------------------
extern "C" void kernel_launch(void* const* d_in, const int* in_sizes, int n_in,
                              void* d_out, int out_size)
{
    (void)in_sizes; (void)n_in; (void)out_size;
    const float* x      = (const float*)d_in[0];
    const float* s      = (const float*)d_in[1];
    const float* fc1w   = (const float*)d_in[2];
    const float* fc1b   = (const float*)d_in[3];
    const float* alpha1 = (const float*)d_in[4];
    const float* c1v    = (const float*)d_in[5];
    const float* c1g    = (const float*)d_in[6];
    const float* c1b    = (const float*)d_in[7];
    const float* fc2w   = (const float*)d_in[8];
    const float* fc2b   = (const float*)d_in[9];
    const float* alpha2 = (const float*)d_in[10];
    const float* c2v    = (const float*)d_in[11];
    const float* c2g    = (const float*)d_in[12];
    const float* c2b    = (const float*)d_in[13];
    float* out = (float*)d_out;

    float *T1, *T2, *X1, *W, *GB, *MU, *RS;
    cudaGetSymbolAddress((void**)&T1, g_T1);
    cudaGetSymbolAddress((void**)&T2, g_T2);
    cudaGetSymbolAddress((void**)&X1, g_X1);
    cudaGetSymbolAddress((void**)&W,  g_W);
    cudaGetSymbolAddress((void**)&GB, g_GB);
    cudaGetSymbolAddress((void**)&MU, g_MU);
    cudaGetSymbolAddress((void**)&RS, g_RS);

    // setup: style affines (6 layers) + normalized weights (6 convs)
    style_kernel<<<6 * Bb, 256>>>(s, fc1w, fc1b, fc2w, fc2b, GB);
    wnorm_kernel<<<6 * (Cc / 128), 128>>>(c1v, c1g, c2v, c2g, W);

    const int dils[3] = {1, 3, 5};
    const size_t N4 = (size_t)Bb * Tt * Cc / 4;
    const int ew_blocks = (int)(N4 / 256);
    dim3 conv_grid((Bb * Tt) / BM, Cc / BN);
    dim3 stat_grid(Cc / 32, Bb);

    for (int i = 0; i < 3; i++) {
        const float* xin  = (i == 0) ? x : X1;
        float*       xout = (i == 2) ? out : X1;
        const size_t kcc = (size_t)Kt * Cc * Cc;

        stats_kernel<<<stat_grid, 256>>>(xin, MU, RS);
        adain_snake_kernel<<<ew_blocks, 256>>>(xin, MU, RS,
                                               GB + (size_t)(2 * i) * Bb * 2 * Cc,
                                               alpha1 + (size_t)i * Cc, T1);
        conv_kernel<<<conv_grid, 256>>>(T1, W + (size_t)(2 * i) * kcc,
                                        c1b + (size_t)i * Cc, (const float*)0,
                                        T2, dils[i]);
        stats_kernel<<<stat_grid, 256>>>(T2, MU, RS);
        adain_snake_kernel<<<ew_blocks, 256>>>(T2, MU, RS,
                                               GB + (size_t)(2 * i + 1) * Bb * 2 * Cc,
                                               alpha2 + (size_t)i * Cc, T1);
        conv_kernel<<<conv_grid, 256>>>(T1, W + (size_t)(2 * i + 1) * kcc,
                                        c2b + (size_t)i * Cc, xin,
                                        xout, 1);
    }
}

// round 4
// speedup vs baseline: 2.6778x; 2.6778x over previous
#include <cuda_runtime.h>
#include <cuda_bf16.h>
#include <math.h>
#include <stdint.h>

// Problem constants
#define Bb 8
#define Tt 4096
#define Cc 512
#define Kt 3
#define Ss 64

// Conv GEMM tiling
#define PITCH 72                         // bf16 elems per smem row (64 data + 8 pad)
#define TILE_BYTES (128 * PITCH * 2)     // 18432 B: one 128x64 bf16 tile
#define STAGE_BYTES (4 * TILE_BYTES)     // Ahi, Alo, Whi, Wlo
#define CONV_SMEM (2 * STAGE_BYTES)      // double buffered: 147456 B
#define NSTAGES 24                       // 3 taps x (512/64)

// ---------------- scratch (device globals; no runtime allocation) -------------
__device__ __nv_bfloat16 g_Ahi[(size_t)Bb * Tt * Cc];
__device__ __nv_bfloat16 g_Alo[(size_t)Bb * Tt * Cc];
__device__ float g_T2[(size_t)Bb * Tt * Cc];
__device__ float g_X1[(size_t)Bb * Tt * Cc];
__device__ __nv_bfloat16 g_Whi[(size_t)6 * Kt * Cc * Cc]; // [j][tap][cout][cin]
__device__ __nv_bfloat16 g_Wlo[(size_t)6 * Kt * Cc * Cc];
__device__ float g_SC[6 * Cc];
__device__ float g_GB[(size_t)6 * Bb * 2 * Cc];
__device__ float g_MU[Bb * Cc];
__device__ float g_RS[Bb * Cc];

// ================= PTX helpers (portable sm_80+ subset) ========================
__device__ __forceinline__ uint32_t smem_u32(const void* p) {
    uint32_t a;
    asm("{ .reg .u64 t; cvta.to.shared.u64 t, %1; cvt.u32.u64 %0, t; }" : "=r"(a) : "l"(p));
    return a;
}

__device__ __forceinline__ void mma16816(float* d, const uint32_t* a, const uint32_t* b) {
    asm volatile(
        "mma.sync.aligned.m16n8k16.row.col.f32.bf16.bf16.f32 "
        "{%0,%1,%2,%3}, {%4,%5,%6,%7}, {%8,%9}, {%0,%1,%2,%3};"
        : "+f"(d[0]), "+f"(d[1]), "+f"(d[2]), "+f"(d[3])
        : "r"(a[0]), "r"(a[1]), "r"(a[2]), "r"(a[3]), "r"(b[0]), "r"(b[1]));
}

__device__ __forceinline__ void ldsm4(uint32_t* r, uint32_t addr) {
    asm volatile("ldmatrix.sync.aligned.m8n8.x4.shared.b16 {%0,%1,%2,%3}, [%4];"
                 : "=r"(r[0]), "=r"(r[1]), "=r"(r[2]), "=r"(r[3]) : "r"(addr));
}

__device__ __forceinline__ void cp16(uint32_t dst, const void* src) {
    asm volatile("cp.async.cg.shared.global [%0], [%1], 16;" :: "r"(dst), "l"(src));
}
__device__ __forceinline__ void cp16z(uint32_t dst, const void* src, uint32_t n) {
    asm volatile("cp.async.cg.shared.global [%0], [%1], 16, %2;" :: "r"(dst), "l"(src), "r"(n));
}
#define CP_COMMIT() asm volatile("cp.async.commit_group;" ::: "memory")
#define CP_WAIT1()  asm volatile("cp.async.wait_group 1;" ::: "memory")
#define CP_WAIT0()  asm volatile("cp.async.wait_group 0;" ::: "memory")

// ---------------- style MLP ----------------------------------------------------
__global__ void style_kernel(const float* __restrict__ s,
                             const float* __restrict__ fc1w, const float* __restrict__ fc1b,
                             const float* __restrict__ fc2w, const float* __restrict__ fc2b,
                             float* __restrict__ gb)
{
    int j = blockIdx.x / Bb;
    int b = blockIdx.x % Bb;
    int i = j >> 1, layer = j & 1;
    const float* w  = (layer ? fc2w : fc1w) + (size_t)i * Ss * 2 * Cc;
    const float* bi = (layer ? fc2b : fc1b) + (size_t)i * 2 * Cc;

    __shared__ float ss[Ss];
    if (threadIdx.x < Ss) ss[threadIdx.x] = s[b * Ss + threadIdx.x];
    __syncthreads();

    for (int n = threadIdx.x; n < 2 * Cc; n += blockDim.x) {
        float acc = bi[n];
#pragma unroll 8
        for (int k = 0; k < Ss; k++) acc += ss[k] * w[(size_t)k * 2 * Cc + n];
        gb[((size_t)j * Bb + b) * 2 * Cc + n] = acc;
    }
}

// ---------------- weight norm scale per (j, cout) ------------------------------
__global__ void wscale_kernel(const float* __restrict__ c1v, const float* __restrict__ c1g,
                              const float* __restrict__ c2v, const float* __restrict__ c2g,
                              float* __restrict__ sc)
{
    int j = blockIdx.x, co = threadIdx.x;
    int i = j >> 1, layer = j & 1;
    const float* v = (layer ? c2v : c1v) + (size_t)i * Kt * Cc * Cc;
    const float* g = (layer ? c2g : c1g) + (size_t)i * Cc;
    float s = 0.f;
    for (int r = 0; r < Kt * Cc; r++) {
        float t = v[(size_t)r * Cc + co];
        s += t * t;
    }
    sc[j * Cc + co] = g[co] * rsqrtf(s);
}

// ---------------- transpose + split weights to [j][tap][cout][cin] bf16 --------
__global__ void wtrans_kernel(const float* __restrict__ c1v, const float* __restrict__ c2v,
                              const float* __restrict__ sc,
                              __nv_bfloat16* __restrict__ whi, __nv_bfloat16* __restrict__ wlo)
{
    int bz = blockIdx.z;
    int j = bz / 3, tap = bz % 3;
    int i = j >> 1, layer = j & 1;
    const float* v = (layer ? c2v : c1v) + (((size_t)i * Kt + tap) * Cc) * Cc;
    int ci0 = blockIdx.x * 32, co0 = blockIdx.y * 32;

    __shared__ float tile[32][33];
#pragma unroll
    for (int q = 0; q < 4; q++) {
        int ci = ci0 + threadIdx.y + q * 8;
        int co = co0 + threadIdx.x;
        tile[threadIdx.y + q * 8][threadIdx.x] = v[(size_t)ci * Cc + co] * sc[j * Cc + co];
    }
    __syncthreads();
    size_t wb = ((size_t)(j * Kt + tap)) * Cc * Cc;
#pragma unroll
    for (int q = 0; q < 4; q++) {
        int co = co0 + threadIdx.y + q * 8;
        int ci = ci0 + threadIdx.x;
        float w = tile[threadIdx.x][threadIdx.y + q * 8];
        __nv_bfloat16 h = __float2bfloat16(w);
        float rem = w - __bfloat162float(h);
        whi[wb + (size_t)co * Cc + ci] = h;
        wlo[wb + (size_t)co * Cc + ci] = __float2bfloat16(rem);
    }
}

// ---------------- instance-norm stats over time per (b, c) --------------------
__global__ void stats_kernel(const float* __restrict__ x,
                             float* __restrict__ mu, float* __restrict__ rs)
{
    int b  = blockIdx.y;
    int c0 = blockIdx.x * 32;
    int cl = threadIdx.x & 31;
    int tg = threadIdx.x >> 5;
    const float* base = x + (size_t)b * Tt * Cc + c0 + cl;

    float s = 0.f, s2 = 0.f;
    for (int t = tg; t < Tt; t += 8) {
        float v = base[(size_t)t * Cc];
        s += v; s2 += v * v;
    }
    __shared__ float sh[2][8][32];
    sh[0][tg][cl] = s; sh[1][tg][cl] = s2;
    __syncthreads();
    if (tg == 0) {
        float S = 0.f, S2 = 0.f;
#pragma unroll
        for (int q = 0; q < 8; q++) { S += sh[0][q][cl]; S2 += sh[1][q][cl]; }
        float m   = S * (1.0f / Tt);
        float var = S2 * (1.0f / Tt) - m * m;
        mu[b * Cc + c0 + cl] = m;
        rs[b * Cc + c0 + cl] = rsqrtf(var + 1e-5f);
    }
}

// ---------------- adain + snake, emitting bf16 hi/lo split --------------------
__global__ void adain_snake_split_kernel(const float* __restrict__ x,
                                         const float* __restrict__ mu, const float* __restrict__ rs,
                                         const float* __restrict__ gb,
                                         const float* __restrict__ alpha,
                                         __nv_bfloat16* __restrict__ hi,
                                         __nv_bfloat16* __restrict__ lo)
{
    size_t idx = (size_t)blockIdx.x * blockDim.x + threadIdx.x;   // float4 index
    size_t e = idx * 4;
    int c = (int)(e & (Cc - 1));
    int b = (int)(e >> 21);

    float4 xv = ((const float4*)x)[idx];
    float4 gv = *(const float4*)(gb + (size_t)b * 2 * Cc + c);
    float4 bv = *(const float4*)(gb + (size_t)b * 2 * Cc + Cc + c);
    float4 mv = *(const float4*)(mu + b * Cc + c);
    float4 rv = *(const float4*)(rs + b * Cc + c);
    float4 av = *(const float4*)(alpha + c);

    float o[4];
    {
        float xn = (xv.x - mv.x) * rv.x;
        float v  = (1.0f + gv.x) * xn + bv.x;
        float sn = sinf(av.x * v);
        o[0] = v + (sn * sn) / av.x;
    }
    {
        float xn = (xv.y - mv.y) * rv.y;
        float v  = (1.0f + gv.y) * xn + bv.y;
        float sn = sinf(av.y * v);
        o[1] = v + (sn * sn) / av.y;
    }
    {
        float xn = (xv.z - mv.z) * rv.z;
        float v  = (1.0f + gv.z) * xn + bv.z;
        float sn = sinf(av.z * v);
        o[2] = v + (sn * sn) / av.z;
    }
    {
        float xn = (xv.w - mv.w) * rv.w;
        float v  = (1.0f + gv.w) * xn + bv.w;
        float sn = sinf(av.w * v);
        o[3] = v + (sn * sn) / av.w;
    }

    uint32_t hp[2], lp[2];
#pragma unroll
    for (int q = 0; q < 2; q++) {
        __nv_bfloat16 h0 = __float2bfloat16(o[2 * q]);
        __nv_bfloat16 h1 = __float2bfloat16(o[2 * q + 1]);
        float r0 = o[2 * q]     - __bfloat162float(h0);
        float r1 = o[2 * q + 1] - __bfloat162float(h1);
        __nv_bfloat16 l0 = __float2bfloat16(r0);
        __nv_bfloat16 l1 = __float2bfloat16(r1);
        hp[q] = (uint32_t)__bfloat16_as_ushort(h0) | ((uint32_t)__bfloat16_as_ushort(h1) << 16);
        lp[q] = (uint32_t)__bfloat16_as_ushort(l0) | ((uint32_t)__bfloat16_as_ushort(l1) << 16);
    }
    ((uint2*)hi)[idx] = make_uint2(hp[0], hp[1]);
    ((uint2*)lo)[idx] = make_uint2(lp[0], lp[1]);
}

// ---------------- dilated conv: mma.sync bf16-split GEMM -----------------------
__device__ __forceinline__ void load_stage(uint32_t sdst,
    const __nv_bfloat16* __restrict__ Ahi, const __nv_bfloat16* __restrict__ Alo,
    const __nv_bfloat16* __restrict__ Whi, const __nv_bfloat16* __restrict__ Wlo,
    int bb, int t0, int tap, int kk, int dil, int block_n, int tid)
{
#pragma unroll
    for (int q = 0; q < 4; q++) {
        int c   = tid + 256 * q;
        int row = c >> 3, k8 = c & 7;
        int tp  = t0 + row + (tap - 1) * dil;
        bool valid = ((unsigned)tp < (unsigned)Tt);
        size_t off = (((size_t)bb << 12) + (size_t)(valid ? tp : 0)) * Cc + kk + k8 * 8;
        uint32_t dst = sdst + row * (PITCH * 2) + k8 * 16;
        uint32_t n = valid ? 16u : 0u;
        cp16z(dst,              Ahi + off, n);
        cp16z(dst + TILE_BYTES, Alo + off, n);
    }
#pragma unroll
    for (int q = 0; q < 4; q++) {
        int c   = tid + 256 * q;
        int row = c >> 3, k8 = c & 7;
        size_t off = ((size_t)(tap * Cc + block_n + row)) * Cc + kk + k8 * 8;
        uint32_t dst = sdst + 2 * TILE_BYTES + row * (PITCH * 2) + k8 * 16;
        cp16(dst,              Whi + off);
        cp16(dst + TILE_BYTES, Wlo + off);
    }
}

__global__ void __launch_bounds__(256, 1)
conv_mma_kernel(const __nv_bfloat16* __restrict__ Ahi, const __nv_bfloat16* __restrict__ Alo,
                const __nv_bfloat16* __restrict__ Whi, const __nv_bfloat16* __restrict__ Wlo,
                const float* __restrict__ bias, const float* __restrict__ res,
                float* __restrict__ out, int dil)
{
    extern __shared__ __align__(16) char dsm[];
    const uint32_t sbase = smem_u32(dsm);

    const int tid  = threadIdx.x;
    const int wid  = tid >> 5;
    const int lane = tid & 31;

    const int block_m = blockIdx.x * 128;
    const int block_n = blockIdx.y * 128;
    const int bb = block_m >> 12;
    const int t0 = block_m & (Tt - 1);

    const int wm = (wid >> 2) * 64;   // warp m offset in tile (0 or 64)
    const int wn = (wid & 3) * 32;    // warp n offset in tile (0..96)

    float acc[4][4][4];
#pragma unroll
    for (int i = 0; i < 4; i++)
#pragma unroll
        for (int j = 0; j < 4; j++)
#pragma unroll
            for (int r = 0; r < 4; r++) acc[i][j][r] = 0.f;

    // prologue: stage 0 into buffer 0
    load_stage(sbase, Ahi, Alo, Whi, Wlo, bb, t0, 0, 0, dil, block_n, tid);
    CP_COMMIT();

    for (int s = 0; s < NSTAGES; ++s) {
        const uint32_t sbuf = sbase + (uint32_t)(s & 1) * STAGE_BYTES;
        if (s + 1 < NSTAGES) {
            const int tap = (s + 1) >> 3;
            const int kk  = ((s + 1) & 7) << 6;
            load_stage(sbase + (uint32_t)((s + 1) & 1) * STAGE_BYTES,
                       Ahi, Alo, Whi, Wlo, bb, t0, tap, kk, dil, block_n, tid);
            CP_COMMIT();
            CP_WAIT1();
        } else {
            CP_WAIT0();
        }
        __syncthreads();

        const uint32_t sAh = sbuf;
        const uint32_t sAl = sbuf + TILE_BYTES;
        const uint32_t sWh = sbuf + 2 * TILE_BYTES;
        const uint32_t sWl = sbuf + 3 * TILE_BYTES;

        // ldmatrix lane addressing (all non-trans):
        // A fragment: lanes 0-15 -> m-rows 0-15 @k-base, lanes 16-31 -> same rows @k+8
        const int arow = lane & 15;
        const int ahalf = (lane >> 4) * 8;
        // B fragment (W stored [cout][cin], k contiguous): lanes 0-7 (n0-7,k0),
        // 8-15 (n0-7,k8), 16-23 (n8-15,k0), 24-31 (n8-15,k8) -> regs b0,b1 per n-block
        const int bn = (lane & 7) + ((lane >> 4) & 1) * 8;
        const int bk = ((lane >> 3) & 1) * 8;

#pragma unroll
        for (int ks = 0; ks < 4; ++ks) {
            const int kc = ks * 16;
            uint32_t ah[4][4], al[4][4], bh[2][4], bl[2][4];
#pragma unroll
            for (int i = 0; i < 4; i++) {
                uint32_t aaddr = (uint32_t)((wm + i * 16 + arow) * (PITCH * 2) + (kc + ahalf) * 2);
                ldsm4(ah[i], sAh + aaddr);
                ldsm4(al[i], sAl + aaddr);
            }
#pragma unroll
            for (int j2 = 0; j2 < 2; j2++) {
                uint32_t baddr = (uint32_t)((wn + j2 * 16 + bn) * (PITCH * 2) + (kc + bk) * 2);
                ldsm4(bh[j2], sWh + baddr);
                ldsm4(bl[j2], sWl + baddr);
            }
#pragma unroll
            for (int i = 0; i < 4; i++) {
#pragma unroll
                for (int j = 0; j < 4; j++) {
                    const uint32_t* bhj = &bh[j >> 1][(j & 1) * 2];
                    const uint32_t* blj = &bl[j >> 1][(j & 1) * 2];
                    mma16816(acc[i][j], ah[i], bhj);   // Ahi * Whi
                    mma16816(acc[i][j], ah[i], blj);   // Ahi * Wlo
                    mma16816(acc[i][j], al[i], bhj);   // Alo * Whi
                }
            }
        }
        __syncthreads();
    }

    // epilogue: bias (+ residual), direct to gmem
#pragma unroll
    for (int i = 0; i < 4; i++) {
#pragma unroll
        for (int j = 0; j < 4; j++) {
            const int col  = block_n + wn + j * 8 + (lane & 3) * 2;
            const int row0 = block_m + wm + i * 16 + (lane >> 2);
            const int row1 = row0 + 8;
            const float b0 = bias[col], b1 = bias[col + 1];

            float2 v0 = make_float2(acc[i][j][0] + b0, acc[i][j][1] + b1);
            float2 v1 = make_float2(acc[i][j][2] + b0, acc[i][j][3] + b1);
            if (res) {
                float2 r0 = *(const float2*)(res + (size_t)row0 * Cc + col);
                float2 r1 = *(const float2*)(res + (size_t)row1 * Cc + col);
                v0.x += r0.x; v0.y += r0.y;
                v1.x += r1.x; v1.y += r1.y;
            }
            *(float2*)(out + (size_t)row0 * Cc + col) = v0;
            *(float2*)(out + (size_t)row1 * Cc + col) = v1;
        }
    }
}

// -------------------------------- launch --------------------------------------
extern "C" void kernel_launch(void* const* d_in, const int* in_sizes, int n_in,
                              void* d_out, int out_size)
{
    (void)in_sizes; (void)n_in; (void)out_size;
    const float* x      = (const float*)d_in[0];
    const float* s      = (const float*)d_in[1];
    const float* fc1w   = (const float*)d_in[2];
    const float* fc1b   = (const float*)d_in[3];
    const float* alpha1 = (const float*)d_in[4];
    const float* c1v    = (const float*)d_in[5];
    const float* c1g    = (const float*)d_in[6];
    const float* c1b    = (const float*)d_in[7];
    const float* fc2w   = (const float*)d_in[8];
    const float* fc2b   = (const float*)d_in[9];
    const float* alpha2 = (const float*)d_in[10];
    const float* c2v    = (const float*)d_in[11];
    const float* c2g    = (const float*)d_in[12];
    const float* c2b    = (const float*)d_in[13];
    float* out = (float*)d_out;

    __nv_bfloat16 *Ahi, *Alo, *Whi, *Wlo;
    float *T2, *X1, *SC, *GB, *MU, *RS;
    cudaGetSymbolAddress((void**)&Ahi, g_Ahi);
    cudaGetSymbolAddress((void**)&Alo, g_Alo);
    cudaGetSymbolAddress((void**)&T2,  g_T2);
    cudaGetSymbolAddress((void**)&X1,  g_X1);
    cudaGetSymbolAddress((void**)&Whi, g_Whi);
    cudaGetSymbolAddress((void**)&Wlo, g_Wlo);
    cudaGetSymbolAddress((void**)&SC,  g_SC);
    cudaGetSymbolAddress((void**)&GB,  g_GB);
    cudaGetSymbolAddress((void**)&MU,  g_MU);
    cudaGetSymbolAddress((void**)&RS,  g_RS);

    cudaFuncSetAttribute(conv_mma_kernel,
                         cudaFuncAttributeMaxDynamicSharedMemorySize, CONV_SMEM);

    // setup: style affines, weight-norm scale, weight transpose+split
    style_kernel<<<6 * Bb, 256>>>(s, fc1w, fc1b, fc2w, fc2b, GB);
    wscale_kernel<<<6, Cc>>>(c1v, c1g, c2v, c2g, SC);
    wtrans_kernel<<<dim3(16, 16, 18), dim3(32, 8)>>>(c1v, c2v, SC, Whi, Wlo);

    const int dils[3] = {1, 3, 5};
    const size_t N4 = (size_t)Bb * Tt * Cc / 4;
    const int ew_blocks = (int)(N4 / 256);
    dim3 conv_grid((Bb * Tt) / 128, Cc / 128);
    dim3 stat_grid(Cc / 32, Bb);
    const size_t KCC = (size_t)Kt * Cc * Cc;

    for (int i = 0; i < 3; i++) {
        const float* xin  = (i == 0) ? x : X1;
        float*       xout = (i == 2) ? out : X1;

        stats_kernel<<<stat_grid, 256>>>(xin, MU, RS);
        adain_snake_split_kernel<<<ew_blocks, 256>>>(xin, MU, RS,
                                                     GB + (size_t)(2 * i) * Bb * 2 * Cc,
                                                     alpha1 + (size_t)i * Cc, Ahi, Alo);
        conv_mma_kernel<<<conv_grid, 256, CONV_SMEM>>>(Ahi, Alo,
                                                       Whi + (size_t)(2 * i) * KCC,
                                                       Wlo + (size_t)(2 * i) * KCC,
                                                       c1b + (size_t)i * Cc, (const float*)0,
                                                       T2, dils[i]);
        stats_kernel<<<stat_grid, 256>>>(T2, MU, RS);
        adain_snake_split_kernel<<<ew_blocks, 256>>>(T2, MU, RS,
                                                     GB + (size_t)(2 * i + 1) * Bb * 2 * Cc,
                                                     alpha2 + (size_t)i * Cc, Ahi, Alo);
        conv_mma_kernel<<<conv_grid, 256, CONV_SMEM>>>(Ahi, Alo,
                                                       Whi + (size_t)(2 * i + 1) * KCC,
                                                       Wlo + (size_t)(2 * i + 1) * KCC,
                                                       c2b + (size_t)i * Cc, xin,
                                                       xout, 1);
    }
}

// round 5
// speedup vs baseline: 2.9571x; 1.1043x over previous
#include <cuda_runtime.h>
#include <cuda_bf16.h>
#include <math.h>
#include <stdint.h>

// Problem constants
#define Bb 8
#define Tt 4096
#define Cc 512
#define Kt 3
#define Ss 64

// Conv GEMM tiling
#define PITCH 72                         // bf16 elems per smem row (64 data + 8 pad)
#define TILE_BYTES (128 * PITCH * 2)     // 18432 B: one 128x64 bf16 tile
#define STAGE_BYTES (4 * TILE_BYTES)     // Ahi, Alo, Whi, Wlo
#define CONV_SMEM (2 * STAGE_BYTES)      // double buffered: 147456 B
#define NSTAGES 24                       // 3 taps x (512/64)

// ---------------- scratch (device globals; no runtime allocation) -------------
__device__ __nv_bfloat16 g_Ahi[(size_t)Bb * Tt * Cc];
__device__ __nv_bfloat16 g_Alo[(size_t)Bb * Tt * Cc];
__device__ float g_T2[(size_t)Bb * Tt * Cc];
__device__ float g_X1[(size_t)Bb * Tt * Cc];
__device__ __nv_bfloat16 g_Whi[(size_t)6 * Kt * Cc * Cc]; // [j][tap][cout][cin]
__device__ __nv_bfloat16 g_Wlo[(size_t)6 * Kt * Cc * Cc];
__device__ float g_SC[6 * Cc];
__device__ float g_GB[(size_t)6 * Bb * 2 * Cc];
__device__ float g_MU[Bb * Cc];
__device__ float g_RS[Bb * Cc];
__device__ float g_PS[2 * 32 * Bb * Cc];                  // per-slot partial sums/sumsq
__device__ float g_IA[6 * Cc];                            // 1/alpha per (block,layer)

// ================= PTX helpers (portable sm_80+ subset) ========================
__device__ __forceinline__ uint32_t smem_u32(const void* p) {
    uint32_t a;
    asm("{ .reg .u64 t; cvta.to.shared.u64 t, %1; cvt.u32.u64 %0, t; }" : "=r"(a) : "l"(p));
    return a;
}

__device__ __forceinline__ void mma16816(float* d, const uint32_t* a, const uint32_t* b) {
    asm volatile(
        "mma.sync.aligned.m16n8k16.row.col.f32.bf16.bf16.f32 "
        "{%0,%1,%2,%3}, {%4,%5,%6,%7}, {%8,%9}, {%0,%1,%2,%3};"
        : "+f"(d[0]), "+f"(d[1]), "+f"(d[2]), "+f"(d[3])
        : "r"(a[0]), "r"(a[1]), "r"(a[2]), "r"(a[3]), "r"(b[0]), "r"(b[1]));
}

__device__ __forceinline__ void ldsm4(uint32_t* r, uint32_t addr) {
    asm volatile("ldmatrix.sync.aligned.m8n8.x4.shared.b16 {%0,%1,%2,%3}, [%4];"
                 : "=r"(r[0]), "=r"(r[1]), "=r"(r[2]), "=r"(r[3]) : "r"(addr));
}

__device__ __forceinline__ void cp16(uint32_t dst, const void* src) {
    asm volatile("cp.async.cg.shared.global [%0], [%1], 16;" :: "r"(dst), "l"(src));
}
__device__ __forceinline__ void cp16z(uint32_t dst, const void* src, uint32_t n) {
    asm volatile("cp.async.cg.shared.global [%0], [%1], 16, %2;" :: "r"(dst), "l"(src), "r"(n));
}
#define CP_COMMIT() asm volatile("cp.async.commit_group;" ::: "memory")
#define CP_WAIT1()  asm volatile("cp.async.wait_group 1;" ::: "memory")
#define CP_WAIT0()  asm volatile("cp.async.wait_group 0;" ::: "memory")

// ---------------- style MLP ----------------------------------------------------
__global__ void style_kernel(const float* __restrict__ s,
                             const float* __restrict__ fc1w, const float* __restrict__ fc1b,
                             const float* __restrict__ fc2w, const float* __restrict__ fc2b,
                             float* __restrict__ gb)
{
    int j = blockIdx.x / Bb;
    int b = blockIdx.x % Bb;
    int i = j >> 1, layer = j & 1;
    const float* w  = (layer ? fc2w : fc1w) + (size_t)i * Ss * 2 * Cc;
    const float* bi = (layer ? fc2b : fc1b) + (size_t)i * 2 * Cc;

    __shared__ float ss[Ss];
    if (threadIdx.x < Ss) ss[threadIdx.x] = s[b * Ss + threadIdx.x];
    __syncthreads();

    for (int n = threadIdx.x; n < 2 * Cc; n += blockDim.x) {
        float acc = bi[n];
#pragma unroll 8
        for (int k = 0; k < Ss; k++) acc += ss[k] * w[(size_t)k * 2 * Cc + n];
        gb[((size_t)j * Bb + b) * 2 * Cc + n] = acc;
    }
}

// ---------------- weight norm scale per (j, cout) ------------------------------
__global__ void wscale_kernel(const float* __restrict__ c1v, const float* __restrict__ c1g,
                              const float* __restrict__ c2v, const float* __restrict__ c2g,
                              float* __restrict__ sc)
{
    int j = blockIdx.x, co = threadIdx.x;
    int i = j >> 1, layer = j & 1;
    const float* v = (layer ? c2v : c1v) + (size_t)i * Kt * Cc * Cc;
    const float* g = (layer ? c2g : c1g) + (size_t)i * Cc;
    float s = 0.f;
    for (int r = 0; r < Kt * Cc; r++) {
        float t = v[(size_t)r * Cc + co];
        s += t * t;
    }
    sc[j * Cc + co] = g[co] * rsqrtf(s);
}

// ---------------- 1/alpha precompute -------------------------------------------
__global__ void inva_kernel(const float* __restrict__ alpha1, const float* __restrict__ alpha2,
                            float* __restrict__ ia)
{
    int j = blockIdx.x;
    int i = j >> 1, layer = j & 1;
    const float* a = (layer ? alpha2 : alpha1) + (size_t)i * Cc;
    ia[j * Cc + threadIdx.x] = 1.0f / a[threadIdx.x];
}

// ---------------- transpose + split weights to [j][tap][cout][cin] bf16 --------
__global__ void wtrans_kernel(const float* __restrict__ c1v, const float* __restrict__ c2v,
                              const float* __restrict__ sc,
                              __nv_bfloat16* __restrict__ whi, __nv_bfloat16* __restrict__ wlo)
{
    int bz = blockIdx.z;
    int j = bz / 3, tap = bz % 3;
    int i = j >> 1, layer = j & 1;
    const float* v = (layer ? c2v : c1v) + (((size_t)i * Kt + tap) * Cc) * Cc;
    int ci0 = blockIdx.x * 32, co0 = blockIdx.y * 32;

    __shared__ float tile[32][33];
#pragma unroll
    for (int q = 0; q < 4; q++) {
        int ci = ci0 + threadIdx.y + q * 8;
        int co = co0 + threadIdx.x;
        tile[threadIdx.y + q * 8][threadIdx.x] = v[(size_t)ci * Cc + co] * sc[j * Cc + co];
    }
    __syncthreads();
    size_t wb = ((size_t)(j * Kt + tap)) * Cc * Cc;
#pragma unroll
    for (int q = 0; q < 4; q++) {
        int co = co0 + threadIdx.y + q * 8;
        int ci = ci0 + threadIdx.x;
        float w = tile[threadIdx.x][threadIdx.y + q * 8];
        __nv_bfloat16 h = __float2bfloat16(w);
        float rem = w - __bfloat162float(h);
        whi[wb + (size_t)co * Cc + ci] = h;
        wlo[wb + (size_t)co * Cc + ci] = __float2bfloat16(rem);
    }
}

// ---------------- initial stats partials on x (slot-parallel) ------------------
__global__ void initstats_kernel(const float* __restrict__ x, float* __restrict__ ps)
{
    int si = blockIdx.x;           // 0..31 time slot
    int b  = blockIdx.y;
    int c  = threadIdx.x;          // 0..511
    const float* p = x + (((size_t)b * Tt) + si * 128) * Cc + c;
    float S = 0.f, S2 = 0.f;
#pragma unroll 4
    for (int t = 0; t < 128; t++) {
        float v = p[(size_t)t * Cc];
        S += v; S2 += v * v;
    }
    ps[((size_t)si * Bb + b) * Cc + c]        = S;
    ps[((size_t)(32 + si) * Bb + b) * Cc + c] = S2;
}

// ---------------- finalize: partials -> mu, rsqrt(var+eps) ---------------------
__global__ void finalize_kernel(const float* __restrict__ ps,
                                float* __restrict__ mu, float* __restrict__ rs)
{
    int idx = blockIdx.x * blockDim.x + threadIdx.x;   // 0..4095
    int b = idx >> 9, c = idx & 511;
    float S = 0.f, S2 = 0.f;
#pragma unroll
    for (int si = 0; si < 32; si++) {
        S  += ps[((size_t)si * Bb + b) * Cc + c];
        S2 += ps[((size_t)(32 + si) * Bb + b) * Cc + c];
    }
    float m   = S * (1.0f / Tt);
    float var = S2 * (1.0f / Tt) - m * m;
    mu[idx] = m;
    rs[idx] = rsqrtf(var + 1e-5f);
}

// ---------------- adain + snake, emitting bf16 hi/lo split --------------------
__global__ void adain_snake_split_kernel(const float* __restrict__ x,
                                         const float* __restrict__ mu, const float* __restrict__ rs,
                                         const float* __restrict__ gb,
                                         const float* __restrict__ alpha,
                                         const float* __restrict__ inva,
                                         __nv_bfloat16* __restrict__ hi,
                                         __nv_bfloat16* __restrict__ lo)
{
    size_t idx = (size_t)blockIdx.x * blockDim.x + threadIdx.x;   // float4 index
    size_t e = idx * 4;
    int c = (int)(e & (Cc - 1));
    int b = (int)(e >> 21);

    float4 xv = ((const float4*)x)[idx];
    float4 gv = *(const float4*)(gb + (size_t)b * 2 * Cc + c);
    float4 bv = *(const float4*)(gb + (size_t)b * 2 * Cc + Cc + c);
    float4 mv = *(const float4*)(mu + b * Cc + c);
    float4 rv = *(const float4*)(rs + b * Cc + c);
    float4 av = *(const float4*)(alpha + c);
    float4 iv = *(const float4*)(inva + c);

    float o[4];
    {
        float xn = (xv.x - mv.x) * rv.x;
        float v  = (1.0f + gv.x) * xn + bv.x;
        float sn = sinf(av.x * v);
        o[0] = v + sn * sn * iv.x;
    }
    {
        float xn = (xv.y - mv.y) * rv.y;
        float v  = (1.0f + gv.y) * xn + bv.y;
        float sn = sinf(av.y * v);
        o[1] = v + sn * sn * iv.y;
    }
    {
        float xn = (xv.z - mv.z) * rv.z;
        float v  = (1.0f + gv.z) * xn + bv.z;
        float sn = sinf(av.z * v);
        o[2] = v + sn * sn * iv.z;
    }
    {
        float xn = (xv.w - mv.w) * rv.w;
        float v  = (1.0f + gv.w) * xn + bv.w;
        float sn = sinf(av.w * v);
        o[3] = v + sn * sn * iv.w;
    }

    uint32_t hp[2], lp[2];
#pragma unroll
    for (int q = 0; q < 2; q++) {
        __nv_bfloat16 h0 = __float2bfloat16(o[2 * q]);
        __nv_bfloat16 h1 = __float2bfloat16(o[2 * q + 1]);
        float r0 = o[2 * q]     - __bfloat162float(h0);
        float r1 = o[2 * q + 1] - __bfloat162float(h1);
        __nv_bfloat16 l0 = __float2bfloat16(r0);
        __nv_bfloat16 l1 = __float2bfloat16(r1);
        hp[q] = (uint32_t)__bfloat16_as_ushort(h0) | ((uint32_t)__bfloat16_as_ushort(h1) << 16);
        lp[q] = (uint32_t)__bfloat16_as_ushort(l0) | ((uint32_t)__bfloat16_as_ushort(l1) << 16);
    }
    ((uint2*)hi)[idx] = make_uint2(hp[0], hp[1]);
    ((uint2*)lo)[idx] = make_uint2(lp[0], lp[1]);
}

// ---------------- dilated conv: mma.sync bf16-split GEMM -----------------------
__device__ __forceinline__ void load_stage(uint32_t sdst,
    const __nv_bfloat16* __restrict__ Ahi, const __nv_bfloat16* __restrict__ Alo,
    const __nv_bfloat16* __restrict__ Whi, const __nv_bfloat16* __restrict__ Wlo,
    int bb, int t0, int tap, int kk, int dil, int block_n, int tid)
{
#pragma unroll
    for (int q = 0; q < 4; q++) {
        int c   = tid + 256 * q;
        int row = c >> 3, k8 = c & 7;
        int tp  = t0 + row + (tap - 1) * dil;
        bool valid = ((unsigned)tp < (unsigned)Tt);
        size_t off = (((size_t)bb << 12) + (size_t)(valid ? tp : 0)) * Cc + kk + k8 * 8;
        uint32_t dst = sdst + row * (PITCH * 2) + k8 * 16;
        uint32_t n = valid ? 16u : 0u;
        cp16z(dst,              Ahi + off, n);
        cp16z(dst + TILE_BYTES, Alo + off, n);
    }
#pragma unroll
    for (int q = 0; q < 4; q++) {
        int c   = tid + 256 * q;
        int row = c >> 3, k8 = c & 7;
        size_t off = ((size_t)(tap * Cc + block_n + row)) * Cc + kk + k8 * 8;
        uint32_t dst = sdst + 2 * TILE_BYTES + row * (PITCH * 2) + k8 * 16;
        cp16(dst,              Whi + off);
        cp16(dst + TILE_BYTES, Wlo + off);
    }
}

__global__ void __launch_bounds__(256, 1)
conv_mma_kernel(const __nv_bfloat16* __restrict__ Ahi, const __nv_bfloat16* __restrict__ Alo,
                const __nv_bfloat16* __restrict__ Whi, const __nv_bfloat16* __restrict__ Wlo,
                const float* __restrict__ bias, const float* __restrict__ res,
                float* __restrict__ out, float* __restrict__ statsPart, int dil)
{
    extern __shared__ __align__(16) char dsm[];
    const uint32_t sbase = smem_u32(dsm);

    const int tid  = threadIdx.x;
    const int wid  = tid >> 5;
    const int lane = tid & 31;

    const int block_m = blockIdx.x * 128;
    const int block_n = blockIdx.y * 128;
    const int bb = block_m >> 12;
    const int t0 = block_m & (Tt - 1);

    const int wm = (wid >> 2) * 64;   // warp m offset in tile (0 or 64)
    const int wn = (wid & 3) * 32;    // warp n offset in tile (0..96)

    float acc[4][4][4];
#pragma unroll
    for (int i = 0; i < 4; i++)
#pragma unroll
        for (int j = 0; j < 4; j++)
#pragma unroll
            for (int r = 0; r < 4; r++) acc[i][j][r] = 0.f;

    // prologue: stage 0 into buffer 0
    load_stage(sbase, Ahi, Alo, Whi, Wlo, bb, t0, 0, 0, dil, block_n, tid);
    CP_COMMIT();

    for (int s = 0; s < NSTAGES; ++s) {
        const uint32_t sbuf = sbase + (uint32_t)(s & 1) * STAGE_BYTES;
        if (s + 1 < NSTAGES) {
            const int tap = (s + 1) >> 3;
            const int kk  = ((s + 1) & 7) << 6;
            load_stage(sbase + (uint32_t)((s + 1) & 1) * STAGE_BYTES,
                       Ahi, Alo, Whi, Wlo, bb, t0, tap, kk, dil, block_n, tid);
            CP_COMMIT();
            CP_WAIT1();
        } else {
            CP_WAIT0();
        }
        __syncthreads();

        const uint32_t sAh = sbuf;
        const uint32_t sAl = sbuf + TILE_BYTES;
        const uint32_t sWh = sbuf + 2 * TILE_BYTES;
        const uint32_t sWl = sbuf + 3 * TILE_BYTES;

        // ldmatrix lane addressing (all non-trans)
        const int arow = lane & 15;
        const int ahalf = (lane >> 4) * 8;
        const int bn = (lane & 7) + ((lane >> 4) & 1) * 8;
        const int bk = ((lane >> 3) & 1) * 8;

#pragma unroll
        for (int ks = 0; ks < 4; ++ks) {
            const int kc = ks * 16;
            uint32_t ah[4][4], al[4][4], bh[2][4], bl[2][4];
#pragma unroll
            for (int i = 0; i < 4; i++) {
                uint32_t aaddr = (uint32_t)((wm + i * 16 + arow) * (PITCH * 2) + (kc + ahalf) * 2);
                ldsm4(ah[i], sAh + aaddr);
                ldsm4(al[i], sAl + aaddr);
            }
#pragma unroll
            for (int j2 = 0; j2 < 2; j2++) {
                uint32_t baddr = (uint32_t)((wn + j2 * 16 + bn) * (PITCH * 2) + (kc + bk) * 2);
                ldsm4(bh[j2], sWh + baddr);
                ldsm4(bl[j2], sWl + baddr);
            }
#pragma unroll
            for (int i = 0; i < 4; i++) {
#pragma unroll
                for (int j = 0; j < 4; j++) {
                    const uint32_t* bhj = &bh[j >> 1][(j & 1) * 2];
                    const uint32_t* blj = &bl[j >> 1][(j & 1) * 2];
                    mma16816(acc[i][j], ah[i], bhj);   // Ahi * Whi
                    mma16816(acc[i][j], ah[i], blj);   // Ahi * Wlo
                    mma16816(acc[i][j], al[i], bhj);   // Alo * Whi
                }
            }
        }
        __syncthreads();
    }

    // epilogue: bias (+ residual) + optional per-column stats partials
    float cs[4][2], cq[4][2];
#pragma unroll
    for (int j = 0; j < 4; j++) { cs[j][0] = cs[j][1] = cq[j][0] = cq[j][1] = 0.f; }

#pragma unroll
    for (int i = 0; i < 4; i++) {
#pragma unroll
        for (int j = 0; j < 4; j++) {
            const int col  = block_n + wn + j * 8 + (lane & 3) * 2;
            const int row0 = block_m + wm + i * 16 + (lane >> 2);
            const int row1 = row0 + 8;
            const float b0 = bias[col], b1 = bias[col + 1];

            float2 v0 = make_float2(acc[i][j][0] + b0, acc[i][j][1] + b1);
            float2 v1 = make_float2(acc[i][j][2] + b0, acc[i][j][3] + b1);
            if (res) {
                float2 r0 = *(const float2*)(res + (size_t)row0 * Cc + col);
                float2 r1 = *(const float2*)(res + (size_t)row1 * Cc + col);
                v0.x += r0.x; v0.y += r0.y;
                v1.x += r1.x; v1.y += r1.y;
            }
            *(float2*)(out + (size_t)row0 * Cc + col) = v0;
            *(float2*)(out + (size_t)row1 * Cc + col) = v1;

            cs[j][0] += v0.x + v1.x;
            cs[j][1] += v0.y + v1.y;
            cq[j][0] += v0.x * v0.x + v1.x * v1.x;
            cq[j][1] += v0.y * v0.y + v1.y * v1.y;
        }
    }

    if (statsPart) {
        // reduce over the 8 row-lanes (lane bits 2..4)
#pragma unroll
        for (int j = 0; j < 4; j++)
#pragma unroll
            for (int k = 0; k < 2; k++) {
#pragma unroll
                for (int off = 4; off < 32; off <<= 1) {
                    cs[j][k] += __shfl_xor_sync(0xffffffffu, cs[j][k], off);
                    cq[j][k] += __shfl_xor_sync(0xffffffffu, cq[j][k], off);
                }
            }
        float* ssum = (float*)dsm;          // [8][32]
        float* ssq  = ssum + 256;
        if (lane < 4) {
#pragma unroll
            for (int j = 0; j < 4; j++)
#pragma unroll
                for (int k = 0; k < 2; k++) {
                    int cc = j * 8 + lane * 2 + k;
                    ssum[wid * 32 + cc] = cs[j][k];
                    ssq [wid * 32 + cc] = cq[j][k];
                }
        }
        __syncthreads();
        const int si = (block_m >> 7) & 31;
        if (tid < 128) {
            int w = tid >> 5, cw = tid & 31;
            statsPart[((size_t)si * Bb + bb) * Cc + block_n + tid] =
                ssum[w * 32 + cw] + ssum[(w + 4) * 32 + cw];
        } else {
            int t2 = tid - 128;
            int w = t2 >> 5, cw = t2 & 31;
            statsPart[((size_t)(32 + si) * Bb + bb) * Cc + block_n + t2] =
                ssq[w * 32 + cw] + ssq[(w + 4) * 32 + cw];
        }
    }
}

// -------------------------------- launch --------------------------------------
extern "C" void kernel_launch(void* const* d_in, const int* in_sizes, int n_in,
                              void* d_out, int out_size)
{
    (void)in_sizes; (void)n_in; (void)out_size;
    const float* x      = (const float*)d_in[0];
    const float* s      = (const float*)d_in[1];
    const float* fc1w   = (const float*)d_in[2];
    const float* fc1b   = (const float*)d_in[3];
    const float* alpha1 = (const float*)d_in[4];
    const float* c1v    = (const float*)d_in[5];
    const float* c1g    = (const float*)d_in[6];
    const float* c1b    = (const float*)d_in[7];
    const float* fc2w   = (const float*)d_in[8];
    const float* fc2b   = (const float*)d_in[9];
    const float* alpha2 = (const float*)d_in[10];
    const float* c2v    = (const float*)d_in[11];
    const float* c2g    = (const float*)d_in[12];
    const float* c2b    = (const float*)d_in[13];
    float* out = (float*)d_out;

    __nv_bfloat16 *Ahi, *Alo, *Whi, *Wlo;
    float *T2, *X1, *SC, *GB, *MU, *RS, *PS, *IA;
    cudaGetSymbolAddress((void**)&Ahi, g_Ahi);
    cudaGetSymbolAddress((void**)&Alo, g_Alo);
    cudaGetSymbolAddress((void**)&T2,  g_T2);
    cudaGetSymbolAddress((void**)&X1,  g_X1);
    cudaGetSymbolAddress((void**)&Whi, g_Whi);
    cudaGetSymbolAddress((void**)&Wlo, g_Wlo);
    cudaGetSymbolAddress((void**)&SC,  g_SC);
    cudaGetSymbolAddress((void**)&GB,  g_GB);
    cudaGetSymbolAddress((void**)&MU,  g_MU);
    cudaGetSymbolAddress((void**)&RS,  g_RS);
    cudaGetSymbolAddress((void**)&PS,  g_PS);
    cudaGetSymbolAddress((void**)&IA,  g_IA);

    cudaFuncSetAttribute(conv_mma_kernel,
                         cudaFuncAttributeMaxDynamicSharedMemorySize, CONV_SMEM);

    // setup: style affines, weight-norm scale, inv-alpha, weight transpose+split
    style_kernel<<<6 * Bb, 256>>>(s, fc1w, fc1b, fc2w, fc2b, GB);
    wscale_kernel<<<6, Cc>>>(c1v, c1g, c2v, c2g, SC);
    inva_kernel<<<6, Cc>>>(alpha1, alpha2, IA);
    wtrans_kernel<<<dim3(16, 16, 18), dim3(32, 8)>>>(c1v, c2v, SC, Whi, Wlo);

    const int dils[3] = {1, 3, 5};
    const size_t N4 = (size_t)Bb * Tt * Cc / 4;
    const int ew_blocks = (int)(N4 / 256);
    dim3 conv_grid((Bb * Tt) / 128, Cc / 128);
    const size_t KCC = (size_t)Kt * Cc * Cc;

    // initial stats on x
    initstats_kernel<<<dim3(32, Bb), 512>>>(x, PS);
    finalize_kernel<<<8, 512>>>(PS, MU, RS);

    for (int i = 0; i < 3; i++) {
        const float* xin  = (i == 0) ? x : X1;
        float*       xout = (i == 2) ? out : X1;

        adain_snake_split_kernel<<<ew_blocks, 256>>>(xin, MU, RS,
                                                     GB + (size_t)(2 * i) * Bb * 2 * Cc,
                                                     alpha1 + (size_t)i * Cc,
                                                     IA + (size_t)(2 * i) * Cc,
                                                     Ahi, Alo);
        conv_mma_kernel<<<conv_grid, 256, CONV_SMEM>>>(Ahi, Alo,
                                                       Whi + (size_t)(2 * i) * KCC,
                                                       Wlo + (size_t)(2 * i) * KCC,
                                                       c1b + (size_t)i * Cc, (const float*)0,
                                                       T2, PS, dils[i]);
        finalize_kernel<<<8, 512>>>(PS, MU, RS);
        adain_snake_split_kernel<<<ew_blocks, 256>>>(T2, MU, RS,
                                                     GB + (size_t)(2 * i + 1) * Bb * 2 * Cc,
                                                     alpha2 + (size_t)i * Cc,
                                                     IA + (size_t)(2 * i + 1) * Cc,
                                                     Ahi, Alo);
        conv_mma_kernel<<<conv_grid, 256, CONV_SMEM>>>(Ahi, Alo,
                                                       Whi + (size_t)(2 * i + 1) * KCC,
                                                       Wlo + (size_t)(2 * i + 1) * KCC,
                                                       c2b + (size_t)i * Cc, xin,
                                                       xout, (i < 2) ? PS : (float*)0, 1);
        if (i < 2) finalize_kernel<<<8, 512>>>(PS, MU, RS);
    }
}

// round 6
// speedup vs baseline: 4.4607x; 1.5085x over previous
#include <cuda_runtime.h>
#include <cuda_fp16.h>
#include <math.h>
#include <stdint.h>

// Problem constants
#define Bb 8
#define Tt 4096
#define Cc 512
#define Kt 3
#define Ss 64

// Conv GEMM tiling
#define PITCH 72                         // fp16 elems per smem row (64 data + 8 pad)
#define TILE_BYTES (128 * PITCH * 2)     // 18432 B: one 128x64 fp16 tile
#define STAGE_BYTES (3 * TILE_BYTES)     // A, Whi, Wlo
#define CONV_SMEM (2 * STAGE_BYTES)      // double buffered: 110592 B
#define NSTAGES 24                       // 3 taps x (512/64)
#define WSCL 2048.0f                     // W pre-scale (2^11) to keep Wlo normal
#define OSCL 0.00048828125f              // 2^-11 epilogue rescale

// ---------------- scratch (device globals; no runtime allocation) -------------
__device__ __half g_A [(size_t)Bb * Tt * Cc];             // 33.5 MB fp16 activations
__device__ float g_T2[(size_t)Bb * Tt * Cc];
__device__ float g_X1[(size_t)Bb * Tt * Cc];
__device__ __half g_Whi[(size_t)6 * Kt * Cc * Cc];        // [j][tap][cout][cin], x2048
__device__ __half g_Wlo[(size_t)6 * Kt * Cc * Cc];
__device__ float g_SC[6 * Cc];
__device__ float g_GB[(size_t)6 * Bb * 2 * Cc];
__device__ float g_MU[Bb * Cc];
__device__ float g_RS[Bb * Cc];
__device__ float g_PS[2 * 32 * Bb * Cc];                  // per-slot partial sums/sumsq
__device__ float g_IA[6 * Cc];                            // 1/alpha per (block,layer)

// ================= PTX helpers (portable sm_80+ subset) ========================
__device__ __forceinline__ uint32_t smem_u32(const void* p) {
    uint32_t a;
    asm("{ .reg .u64 t; cvta.to.shared.u64 t, %1; cvt.u32.u64 %0, t; }" : "=r"(a) : "l"(p));
    return a;
}

__device__ __forceinline__ void mma16816(float* d, const uint32_t* a, const uint32_t* b) {
    asm volatile(
        "mma.sync.aligned.m16n8k16.row.col.f32.f16.f16.f32 "
        "{%0,%1,%2,%3}, {%4,%5,%6,%7}, {%8,%9}, {%0,%1,%2,%3};"
        : "+f"(d[0]), "+f"(d[1]), "+f"(d[2]), "+f"(d[3])
        : "r"(a[0]), "r"(a[1]), "r"(a[2]), "r"(a[3]), "r"(b[0]), "r"(b[1]));
}

__device__ __forceinline__ void ldsm4(uint32_t* r, uint32_t addr) {
    asm volatile("ldmatrix.sync.aligned.m8n8.x4.shared.b16 {%0,%1,%2,%3}, [%4];"
                 : "=r"(r[0]), "=r"(r[1]), "=r"(r[2]), "=r"(r[3]) : "r"(addr));
}

__device__ __forceinline__ void cp16(uint32_t dst, const void* src) {
    asm volatile("cp.async.cg.shared.global [%0], [%1], 16;" :: "r"(dst), "l"(src));
}
__device__ __forceinline__ void cp16z(uint32_t dst, const void* src, uint32_t n) {
    asm volatile("cp.async.cg.shared.global [%0], [%1], 16, %2;" :: "r"(dst), "l"(src), "r"(n));
}
#define CP_COMMIT() asm volatile("cp.async.commit_group;" ::: "memory")
#define CP_WAIT1()  asm volatile("cp.async.wait_group 1;" ::: "memory")
#define CP_WAIT0()  asm volatile("cp.async.wait_group 0;" ::: "memory")

// ---------------- style MLP ----------------------------------------------------
__global__ void style_kernel(const float* __restrict__ s,
                             const float* __restrict__ fc1w, const float* __restrict__ fc1b,
                             const float* __restrict__ fc2w, const float* __restrict__ fc2b,
                             float* __restrict__ gb)
{
    int j = blockIdx.x / Bb;
    int b = blockIdx.x % Bb;
    int i = j >> 1, layer = j & 1;
    const float* w  = (layer ? fc2w : fc1w) + (size_t)i * Ss * 2 * Cc;
    const float* bi = (layer ? fc2b : fc1b) + (size_t)i * 2 * Cc;

    __shared__ float ss[Ss];
    if (threadIdx.x < Ss) ss[threadIdx.x] = s[b * Ss + threadIdx.x];
    __syncthreads();

    for (int n = threadIdx.x; n < 2 * Cc; n += blockDim.x) {
        float acc = bi[n];
#pragma unroll 8
        for (int k = 0; k < Ss; k++) acc += ss[k] * w[(size_t)k * 2 * Cc + n];
        gb[((size_t)j * Bb + b) * 2 * Cc + n] = acc;
    }
}

// ---------------- weight norm scale per (j, cout) ------------------------------
__global__ void wscale_kernel(const float* __restrict__ c1v, const float* __restrict__ c1g,
                              const float* __restrict__ c2v, const float* __restrict__ c2g,
                              float* __restrict__ sc)
{
    int j = blockIdx.x, co = threadIdx.x;
    int i = j >> 1, layer = j & 1;
    const float* v = (layer ? c2v : c1v) + (size_t)i * Kt * Cc * Cc;
    const float* g = (layer ? c2g : c1g) + (size_t)i * Cc;
    float s = 0.f;
    for (int r = 0; r < Kt * Cc; r++) {
        float t = v[(size_t)r * Cc + co];
        s += t * t;
    }
    sc[j * Cc + co] = g[co] * rsqrtf(s);
}

// ---------------- 1/alpha precompute -------------------------------------------
__global__ void inva_kernel(const float* __restrict__ alpha1, const float* __restrict__ alpha2,
                            float* __restrict__ ia)
{
    int j = blockIdx.x;
    int i = j >> 1, layer = j & 1;
    const float* a = (layer ? alpha2 : alpha1) + (size_t)i * Cc;
    ia[j * Cc + threadIdx.x] = 1.0f / a[threadIdx.x];
}

// ---------------- transpose + split weights to [j][tap][cout][cin] fp16 --------
__global__ void wtrans_kernel(const float* __restrict__ c1v, const float* __restrict__ c2v,
                              const float* __restrict__ sc,
                              __half* __restrict__ whi, __half* __restrict__ wlo)
{
    int bz = blockIdx.z;
    int j = bz / 3, tap = bz % 3;
    int i = j >> 1, layer = j & 1;
    const float* v = (layer ? c2v : c1v) + (((size_t)i * Kt + tap) * Cc) * Cc;
    int ci0 = blockIdx.x * 32, co0 = blockIdx.y * 32;

    __shared__ float tile[32][33];
#pragma unroll
    for (int q = 0; q < 4; q++) {
        int ci = ci0 + threadIdx.y + q * 8;
        int co = co0 + threadIdx.x;
        tile[threadIdx.y + q * 8][threadIdx.x] = v[(size_t)ci * Cc + co] * sc[j * Cc + co];
    }
    __syncthreads();
    size_t wb = ((size_t)(j * Kt + tap)) * Cc * Cc;
#pragma unroll
    for (int q = 0; q < 4; q++) {
        int co = co0 + threadIdx.y + q * 8;
        int ci = ci0 + threadIdx.x;
        float w = tile[threadIdx.x][threadIdx.y + q * 8] * WSCL;
        __half h = __float2half_rn(w);
        float rem = w - __half2float(h);
        whi[wb + (size_t)co * Cc + ci] = h;
        wlo[wb + (size_t)co * Cc + ci] = __float2half_rn(rem);
    }
}

// ---------------- initial stats partials on x (slot-parallel) ------------------
__global__ void initstats_kernel(const float* __restrict__ x, float* __restrict__ ps)
{
    int si = blockIdx.x;           // 0..31 time slot
    int b  = blockIdx.y;
    int c  = threadIdx.x;          // 0..511
    const float* p = x + (((size_t)b * Tt) + si * 128) * Cc + c;
    float S = 0.f, S2 = 0.f;
#pragma unroll 4
    for (int t = 0; t < 128; t++) {
        float v = p[(size_t)t * Cc];
        S += v; S2 += v * v;
    }
    ps[((size_t)si * Bb + b) * Cc + c]        = S;
    ps[((size_t)(32 + si) * Bb + b) * Cc + c] = S2;
}

// ---------------- finalize: partials -> mu, rsqrt(var+eps) ---------------------
__global__ void finalize_kernel(const float* __restrict__ ps,
                                float* __restrict__ mu, float* __restrict__ rs)
{
    int idx = blockIdx.x * blockDim.x + threadIdx.x;   // 0..4095
    int b = idx >> 9, c = idx & 511;
    float S = 0.f, S2 = 0.f;
#pragma unroll
    for (int si = 0; si < 32; si++) {
        S  += ps[((size_t)si * Bb + b) * Cc + c];
        S2 += ps[((size_t)(32 + si) * Bb + b) * Cc + c];
    }
    float m   = S * (1.0f / Tt);
    float var = S2 * (1.0f / Tt) - m * m;
    mu[idx] = m;
    rs[idx] = rsqrtf(var + 1e-5f);
}

// ---------------- adain + snake, emitting fp16 ---------------------------------
__global__ void adain_snake_kernel(const float* __restrict__ x,
                                   const float* __restrict__ mu, const float* __restrict__ rs,
                                   const float* __restrict__ gb,
                                   const float* __restrict__ alpha,
                                   const float* __restrict__ inva,
                                   __half* __restrict__ outh)
{
    size_t idx = (size_t)blockIdx.x * blockDim.x + threadIdx.x;   // float4 index
    size_t e = idx * 4;
    int c = (int)(e & (Cc - 1));
    int b = (int)(e >> 21);

    float4 xv = ((const float4*)x)[idx];
    float4 gv = *(const float4*)(gb + (size_t)b * 2 * Cc + c);
    float4 bv = *(const float4*)(gb + (size_t)b * 2 * Cc + Cc + c);
    float4 mv = *(const float4*)(mu + b * Cc + c);
    float4 rv = *(const float4*)(rs + b * Cc + c);
    float4 av = *(const float4*)(alpha + c);
    float4 iv = *(const float4*)(inva + c);

    float o[4];
    {
        float xn = (xv.x - mv.x) * rv.x;
        float v  = (1.0f + gv.x) * xn + bv.x;
        float sn = sinf(av.x * v);
        o[0] = v + sn * sn * iv.x;
    }
    {
        float xn = (xv.y - mv.y) * rv.y;
        float v  = (1.0f + gv.y) * xn + bv.y;
        float sn = sinf(av.y * v);
        o[1] = v + sn * sn * iv.y;
    }
    {
        float xn = (xv.z - mv.z) * rv.z;
        float v  = (1.0f + gv.z) * xn + bv.z;
        float sn = sinf(av.z * v);
        o[2] = v + sn * sn * iv.z;
    }
    {
        float xn = (xv.w - mv.w) * rv.w;
        float v  = (1.0f + gv.w) * xn + bv.w;
        float sn = sinf(av.w * v);
        o[3] = v + sn * sn * iv.w;
    }

    uint32_t p0 = (uint32_t)__half_as_ushort(__float2half_rn(o[0])) |
                  ((uint32_t)__half_as_ushort(__float2half_rn(o[1])) << 16);
    uint32_t p1 = (uint32_t)__half_as_ushort(__float2half_rn(o[2])) |
                  ((uint32_t)__half_as_ushort(__float2half_rn(o[3])) << 16);
    ((uint2*)outh)[idx] = make_uint2(p0, p1);
}

// ---------------- dilated conv: mma.sync fp16 2-term GEMM ----------------------
__device__ __forceinline__ void load_stage(uint32_t sdst,
    const __half* __restrict__ A,
    const __half* __restrict__ Whi, const __half* __restrict__ Wlo,
    int bb, int t0, int tap, int kk, int dil, int block_n, int tid)
{
#pragma unroll
    for (int q = 0; q < 4; q++) {
        int c   = tid + 256 * q;
        int row = c >> 3, k8 = c & 7;
        int tp  = t0 + row + (tap - 1) * dil;
        bool valid = ((unsigned)tp < (unsigned)Tt);
        size_t off = (((size_t)bb << 12) + (size_t)(valid ? tp : 0)) * Cc + kk + k8 * 8;
        uint32_t dst = sdst + row * (PITCH * 2) + k8 * 16;
        cp16z(dst, A + off, valid ? 16u : 0u);
    }
#pragma unroll
    for (int q = 0; q < 4; q++) {
        int c   = tid + 256 * q;
        int row = c >> 3, k8 = c & 7;
        size_t off = ((size_t)(tap * Cc + block_n + row)) * Cc + kk + k8 * 8;
        uint32_t dst = sdst + TILE_BYTES + row * (PITCH * 2) + k8 * 16;
        cp16(dst,              Whi + off);
        cp16(dst + TILE_BYTES, Wlo + off);
    }
}

__global__ void __launch_bounds__(256, 2)
conv_mma_kernel(const __half* __restrict__ A,
                const __half* __restrict__ Whi, const __half* __restrict__ Wlo,
                const float* __restrict__ bias, const float* __restrict__ res,
                float* __restrict__ out, float* __restrict__ statsPart, int dil)
{
    extern __shared__ __align__(16) char dsm[];
    const uint32_t sbase = smem_u32(dsm);

    const int tid  = threadIdx.x;
    const int wid  = tid >> 5;
    const int lane = tid & 31;

    const int block_m = blockIdx.x * 128;
    const int block_n = blockIdx.y * 128;
    const int bb = block_m >> 12;
    const int t0 = block_m & (Tt - 1);

    const int wm = (wid >> 2) * 64;   // warp m offset (0 or 64)
    const int wn = (wid & 3) * 32;    // warp n offset (0..96)

    float acc[4][4][4];
#pragma unroll
    for (int i = 0; i < 4; i++)
#pragma unroll
        for (int j = 0; j < 4; j++)
#pragma unroll
            for (int r = 0; r < 4; r++) acc[i][j][r] = 0.f;

    // prologue: stage 0 into buffer 0
    load_stage(sbase, A, Whi, Wlo, bb, t0, 0, 0, dil, block_n, tid);
    CP_COMMIT();

    for (int s = 0; s < NSTAGES; ++s) {
        const uint32_t sbuf = sbase + (uint32_t)(s & 1) * STAGE_BYTES;
        if (s + 1 < NSTAGES) {
            const int tap = (s + 1) >> 3;
            const int kk  = ((s + 1) & 7) << 6;
            load_stage(sbase + (uint32_t)((s + 1) & 1) * STAGE_BYTES,
                       A, Whi, Wlo, bb, t0, tap, kk, dil, block_n, tid);
            CP_COMMIT();
            CP_WAIT1();
        } else {
            CP_WAIT0();
        }
        __syncthreads();

        const uint32_t sA  = sbuf;
        const uint32_t sWh = sbuf + TILE_BYTES;
        const uint32_t sWl = sbuf + 2 * TILE_BYTES;

        // ldmatrix lane addressing (all non-trans)
        const int arow = lane & 15;
        const int ahalf = (lane >> 4) * 8;
        const int bn = (lane & 7) + ((lane >> 4) & 1) * 8;
        const int bk = ((lane >> 3) & 1) * 8;

#pragma unroll
        for (int ks = 0; ks < 4; ++ks) {
            const int kc = ks * 16;
            uint32_t ah[4][4], bh[2][4], bl[2][4];
#pragma unroll
            for (int i = 0; i < 4; i++) {
                uint32_t aaddr = (uint32_t)((wm + i * 16 + arow) * (PITCH * 2) + (kc + ahalf) * 2);
                ldsm4(ah[i], sA + aaddr);
            }
#pragma unroll
            for (int j2 = 0; j2 < 2; j2++) {
                uint32_t baddr = (uint32_t)((wn + j2 * 16 + bn) * (PITCH * 2) + (kc + bk) * 2);
                ldsm4(bh[j2], sWh + baddr);
                ldsm4(bl[j2], sWl + baddr);
            }
#pragma unroll
            for (int i = 0; i < 4; i++) {
#pragma unroll
                for (int j = 0; j < 4; j++) {
                    const uint32_t* bhj = &bh[j >> 1][(j & 1) * 2];
                    const uint32_t* blj = &bl[j >> 1][(j & 1) * 2];
                    mma16816(acc[i][j], ah[i], bhj);   // A * Whi
                    mma16816(acc[i][j], ah[i], blj);   // A * Wlo
                }
            }
        }
        __syncthreads();
    }

    // epilogue: rescale + bias (+ residual) + optional per-column stats partials
    float cs[4][2], cq[4][2];
#pragma unroll
    for (int j = 0; j < 4; j++) { cs[j][0] = cs[j][1] = cq[j][0] = cq[j][1] = 0.f; }

#pragma unroll
    for (int i = 0; i < 4; i++) {
#pragma unroll
        for (int j = 0; j < 4; j++) {
            const int col  = block_n + wn + j * 8 + (lane & 3) * 2;
            const int row0 = block_m + wm + i * 16 + (lane >> 2);
            const int row1 = row0 + 8;
            const float b0 = bias[col], b1 = bias[col + 1];

            float2 v0 = make_float2(acc[i][j][0] * OSCL + b0, acc[i][j][1] * OSCL + b1);
            float2 v1 = make_float2(acc[i][j][2] * OSCL + b0, acc[i][j][3] * OSCL + b1);
            if (res) {
                float2 r0 = *(const float2*)(res + (size_t)row0 * Cc + col);
                float2 r1 = *(const float2*)(res + (size_t)row1 * Cc + col);
                v0.x += r0.x; v0.y += r0.y;
                v1.x += r1.x; v1.y += r1.y;
            }
            *(float2*)(out + (size_t)row0 * Cc + col) = v0;
            *(float2*)(out + (size_t)row1 * Cc + col) = v1;

            cs[j][0] += v0.x + v1.x;
            cs[j][1] += v0.y + v1.y;
            cq[j][0] += v0.x * v0.x + v1.x * v1.x;
            cq[j][1] += v0.y * v0.y + v1.y * v1.y;
        }
    }

    if (statsPart) {
#pragma unroll
        for (int j = 0; j < 4; j++)
#pragma unroll
            for (int k = 0; k < 2; k++) {
#pragma unroll
                for (int off = 4; off < 32; off <<= 1) {
                    cs[j][k] += __shfl_xor_sync(0xffffffffu, cs[j][k], off);
                    cq[j][k] += __shfl_xor_sync(0xffffffffu, cq[j][k], off);
                }
            }
        float* ssum = (float*)dsm;          // [8][32]
        float* ssq  = ssum + 256;
        if (lane < 4) {
#pragma unroll
            for (int j = 0; j < 4; j++)
#pragma unroll
                for (int k = 0; k < 2; k++) {
                    int cc = j * 8 + lane * 2 + k;
                    ssum[wid * 32 + cc] = cs[j][k];
                    ssq [wid * 32 + cc] = cq[j][k];
                }
        }
        __syncthreads();
        const int si = (block_m >> 7) & 31;
        if (tid < 128) {
            int w = tid >> 5, cw = tid & 31;
            statsPart[((size_t)si * Bb + bb) * Cc + block_n + tid] =
                ssum[w * 32 + cw] + ssum[(w + 4) * 32 + cw];
        } else {
            int t2 = tid - 128;
            int w = t2 >> 5, cw = t2 & 31;
            statsPart[((size_t)(32 + si) * Bb + bb) * Cc + block_n + t2] =
                ssq[w * 32 + cw] + ssq[(w + 4) * 32 + cw];
        }
    }
}

// -------------------------------- launch --------------------------------------
extern "C" void kernel_launch(void* const* d_in, const int* in_sizes, int n_in,
                              void* d_out, int out_size)
{
    (void)in_sizes; (void)n_in; (void)out_size;
    const float* x      = (const float*)d_in[0];
    const float* s      = (const float*)d_in[1];
    const float* fc1w   = (const float*)d_in[2];
    const float* fc1b   = (const float*)d_in[3];
    const float* alpha1 = (const float*)d_in[4];
    const float* c1v    = (const float*)d_in[5];
    const float* c1g    = (const float*)d_in[6];
    const float* c1b    = (const float*)d_in[7];
    const float* fc2w   = (const float*)d_in[8];
    const float* fc2b   = (const float*)d_in[9];
    const float* alpha2 = (const float*)d_in[10];
    const float* c2v    = (const float*)d_in[11];
    const float* c2g    = (const float*)d_in[12];
    const float* c2b    = (const float*)d_in[13];
    float* out = (float*)d_out;

    __half *A, *Whi, *Wlo;
    float *T2, *X1, *SC, *GB, *MU, *RS, *PS, *IA;
    cudaGetSymbolAddress((void**)&A,   g_A);
    cudaGetSymbolAddress((void**)&T2,  g_T2);
    cudaGetSymbolAddress((void**)&X1,  g_X1);
    cudaGetSymbolAddress((void**)&Whi, g_Whi);
    cudaGetSymbolAddress((void**)&Wlo, g_Wlo);
    cudaGetSymbolAddress((void**)&SC,  g_SC);
    cudaGetSymbolAddress((void**)&GB,  g_GB);
    cudaGetSymbolAddress((void**)&MU,  g_MU);
    cudaGetSymbolAddress((void**)&RS,  g_RS);
    cudaGetSymbolAddress((void**)&PS,  g_PS);
    cudaGetSymbolAddress((void**)&IA,  g_IA);

    cudaFuncSetAttribute(conv_mma_kernel,
                         cudaFuncAttributeMaxDynamicSharedMemorySize, CONV_SMEM);

    // setup: style affines, weight-norm scale, inv-alpha, weight transpose+split
    style_kernel<<<6 * Bb, 256>>>(s, fc1w, fc1b, fc2w, fc2b, GB);
    wscale_kernel<<<6, Cc>>>(c1v, c1g, c2v, c2g, SC);
    inva_kernel<<<6, Cc>>>(alpha1, alpha2, IA);
    wtrans_kernel<<<dim3(16, 16, 18), dim3(32, 8)>>>(c1v, c2v, SC, Whi, Wlo);

    const int dils[3] = {1, 3, 5};
    const size_t N4 = (size_t)Bb * Tt * Cc / 4;
    const int ew_blocks = (int)(N4 / 256);
    dim3 conv_grid((Bb * Tt) / 128, Cc / 128);
    const size_t KCC = (size_t)Kt * Cc * Cc;

    // initial stats on x
    initstats_kernel<<<dim3(32, Bb), 512>>>(x, PS);
    finalize_kernel<<<8, 512>>>(PS, MU, RS);

    for (int i = 0; i < 3; i++) {
        const float* xin  = (i == 0) ? x : X1;
        float*       xout = (i == 2) ? out : X1;

        adain_snake_kernel<<<ew_blocks, 256>>>(xin, MU, RS,
                                               GB + (size_t)(2 * i) * Bb * 2 * Cc,
                                               alpha1 + (size_t)i * Cc,
                                               IA + (size_t)(2 * i) * Cc, A);
        conv_mma_kernel<<<conv_grid, 256, CONV_SMEM>>>(A,
                                                       Whi + (size_t)(2 * i) * KCC,
                                                       Wlo + (size_t)(2 * i) * KCC,
                                                       c1b + (size_t)i * Cc, (const float*)0,
                                                       T2, PS, dils[i]);
        finalize_kernel<<<8, 512>>>(PS, MU, RS);
        adain_snake_kernel<<<ew_blocks, 256>>>(T2, MU, RS,
                                               GB + (size_t)(2 * i + 1) * Bb * 2 * Cc,
                                               alpha2 + (size_t)i * Cc,
                                               IA + (size_t)(2 * i + 1) * Cc, A);
        conv_mma_kernel<<<conv_grid, 256, CONV_SMEM>>>(A,
                                                       Whi + (size_t)(2 * i + 1) * KCC,
                                                       Wlo + (size_t)(2 * i + 1) * KCC,
                                                       c2b + (size_t)i * Cc, xin,
                                                       xout, (i < 2) ? PS : (float*)0, 1);
        if (i < 2) finalize_kernel<<<8, 512>>>(PS, MU, RS);
    }
}

// round 7
// speedup vs baseline: 6.9675x; 1.5620x over previous
#include <cuda_runtime.h>
#include <cuda_fp16.h>
#include <math.h>
#include <stdint.h>

// Problem constants
#define Bb 8
#define Tt 4096
#define Cc 512
#define Kt 3
#define Ss 64

// Conv GEMM tiling
#define PITCH 72                         // fp16 elems per smem row (64 data + 8 pad)
#define TILE_BYTES (128 * PITCH * 2)     // 18432 B: one 128x64 fp16 tile
#define STAGE_BYTES (2 * TILE_BYTES)     // A, W
#define CONV_SMEM (2 * STAGE_BYTES)      // double buffered: 73728 B
#define NSTAGES 24                       // 3 taps x (512/64)

// ---------------- scratch (device globals; no runtime allocation) -------------
__device__ __half g_A [(size_t)Bb * Tt * Cc];             // fp16 activations
__device__ float g_T2[(size_t)Bb * Tt * Cc];
__device__ float g_X1[(size_t)Bb * Tt * Cc];
__device__ __half g_W [(size_t)6 * Kt * Cc * Cc];         // [j][tap][cout][cin]
__device__ float g_SC[6 * Cc];
__device__ float g_GB[(size_t)6 * Bb * 2 * Cc];
__device__ float g_MU[Bb * Cc];
__device__ float g_RS[Bb * Cc];
__device__ float g_PS[2 * 32 * Bb * Cc];                  // per-slot partial sums/sumsq
__device__ float g_IA[6 * Cc];                            // 1/alpha per (block,layer)

// ================= PTX helpers (portable sm_80+ subset) ========================
__device__ __forceinline__ uint32_t smem_u32(const void* p) {
    uint32_t a;
    asm("{ .reg .u64 t; cvta.to.shared.u64 t, %1; cvt.u32.u64 %0, t; }" : "=r"(a) : "l"(p));
    return a;
}

__device__ __forceinline__ void mma16816(float* d, const uint32_t* a, const uint32_t* b) {
    asm volatile(
        "mma.sync.aligned.m16n8k16.row.col.f32.f16.f16.f32 "
        "{%0,%1,%2,%3}, {%4,%5,%6,%7}, {%8,%9}, {%0,%1,%2,%3};"
        : "+f"(d[0]), "+f"(d[1]), "+f"(d[2]), "+f"(d[3])
        : "r"(a[0]), "r"(a[1]), "r"(a[2]), "r"(a[3]), "r"(b[0]), "r"(b[1]));
}

__device__ __forceinline__ void ldsm4(uint32_t* r, uint32_t addr) {
    asm volatile("ldmatrix.sync.aligned.m8n8.x4.shared.b16 {%0,%1,%2,%3}, [%4];"
                 : "=r"(r[0]), "=r"(r[1]), "=r"(r[2]), "=r"(r[3]) : "r"(addr));
}

__device__ __forceinline__ void cp16(uint32_t dst, const void* src) {
    asm volatile("cp.async.cg.shared.global [%0], [%1], 16;" :: "r"(dst), "l"(src));
}
__device__ __forceinline__ void cp16z(uint32_t dst, const void* src, uint32_t n) {
    asm volatile("cp.async.cg.shared.global [%0], [%1], 16, %2;" :: "r"(dst), "l"(src), "r"(n));
}
#define CP_COMMIT() asm volatile("cp.async.commit_group;" ::: "memory")
#define CP_WAIT1()  asm volatile("cp.async.wait_group 1;" ::: "memory")
#define CP_WAIT0()  asm volatile("cp.async.wait_group 0;" ::: "memory")

// ---------------- style MLP ----------------------------------------------------
__global__ void style_kernel(const float* __restrict__ s,
                             const float* __restrict__ fc1w, const float* __restrict__ fc1b,
                             const float* __restrict__ fc2w, const float* __restrict__ fc2b,
                             float* __restrict__ gb)
{
    int j = blockIdx.x / Bb;
    int b = blockIdx.x % Bb;
    int i = j >> 1, layer = j & 1;
    const float* w  = (layer ? fc2w : fc1w) + (size_t)i * Ss * 2 * Cc;
    const float* bi = (layer ? fc2b : fc1b) + (size_t)i * 2 * Cc;

    __shared__ float ss[Ss];
    if (threadIdx.x < Ss) ss[threadIdx.x] = s[b * Ss + threadIdx.x];
    __syncthreads();

    for (int n = threadIdx.x; n < 2 * Cc; n += blockDim.x) {
        float acc = bi[n];
#pragma unroll 8
        for (int k = 0; k < Ss; k++) acc += ss[k] * w[(size_t)k * 2 * Cc + n];
        gb[((size_t)j * Bb + b) * 2 * Cc + n] = acc;
    }
}

// ---------------- weight norm scale + 1/alpha -----------------------------------
__global__ void wscale_kernel(const float* __restrict__ c1v, const float* __restrict__ c1g,
                              const float* __restrict__ c2v, const float* __restrict__ c2g,
                              const float* __restrict__ alpha1, const float* __restrict__ alpha2,
                              float* __restrict__ sc, float* __restrict__ ia)
{
    int j = blockIdx.x, co = threadIdx.x;
    int i = j >> 1, layer = j & 1;
    const float* v = (layer ? c2v : c1v) + (size_t)i * Kt * Cc * Cc;
    const float* g = (layer ? c2g : c1g) + (size_t)i * Cc;
    float s = 0.f;
    for (int r = 0; r < Kt * Cc; r++) {
        float t = v[(size_t)r * Cc + co];
        s += t * t;
    }
    sc[j * Cc + co] = g[co] * rsqrtf(s);
    const float* a = (layer ? alpha2 : alpha1) + (size_t)i * Cc;
    ia[j * Cc + co] = 1.0f / a[co];
}

// ---------------- transpose weights to [j][tap][cout][cin] fp16 ----------------
__global__ void wtrans_kernel(const float* __restrict__ c1v, const float* __restrict__ c2v,
                              const float* __restrict__ sc, __half* __restrict__ wout)
{
    int bz = blockIdx.z;
    int j = bz / 3, tap = bz % 3;
    int i = j >> 1, layer = j & 1;
    const float* v = (layer ? c2v : c1v) + (((size_t)i * Kt + tap) * Cc) * Cc;
    int ci0 = blockIdx.x * 32, co0 = blockIdx.y * 32;

    __shared__ float tile[32][33];
#pragma unroll
    for (int q = 0; q < 4; q++) {
        int ci = ci0 + threadIdx.y + q * 8;
        int co = co0 + threadIdx.x;
        tile[threadIdx.y + q * 8][threadIdx.x] = v[(size_t)ci * Cc + co] * sc[j * Cc + co];
    }
    __syncthreads();
    size_t wb = ((size_t)(j * Kt + tap)) * Cc * Cc;
#pragma unroll
    for (int q = 0; q < 4; q++) {
        int co = co0 + threadIdx.y + q * 8;
        int ci = ci0 + threadIdx.x;
        wout[wb + (size_t)co * Cc + ci] = __float2half_rn(tile[threadIdx.x][threadIdx.y + q * 8]);
    }
}

// ---------------- initial stats partials on x (slot-parallel) ------------------
__global__ void initstats_kernel(const float* __restrict__ x, float* __restrict__ ps)
{
    int si = blockIdx.x;           // 0..31 time slot
    int b  = blockIdx.y;
    int c  = threadIdx.x;          // 0..511
    const float* p = x + (((size_t)b * Tt) + si * 128) * Cc + c;
    float S = 0.f, S2 = 0.f;
#pragma unroll 4
    for (int t = 0; t < 128; t++) {
        float v = p[(size_t)t * Cc];
        S += v; S2 += v * v;
    }
    ps[((size_t)si * Bb + b) * Cc + c]        = S;
    ps[((size_t)(32 + si) * Bb + b) * Cc + c] = S2;
}

// ---------------- finalize: partials -> mu, rsqrt(var+eps) ---------------------
__global__ void finalize_kernel(const float* __restrict__ ps,
                                float* __restrict__ mu, float* __restrict__ rs)
{
    int idx = blockIdx.x * blockDim.x + threadIdx.x;   // 0..4095
    int b = idx >> 9, c = idx & 511;
    float S = 0.f, S2 = 0.f;
#pragma unroll
    for (int si = 0; si < 32; si++) {
        S  += ps[((size_t)si * Bb + b) * Cc + c];
        S2 += ps[((size_t)(32 + si) * Bb + b) * Cc + c];
    }
    float m   = S * (1.0f / Tt);
    float var = S2 * (1.0f / Tt) - m * m;
    mu[idx] = m;
    rs[idx] = rsqrtf(var + 1e-5f);
}

// ---------------- adain + snake, emitting fp16 ---------------------------------
__global__ void adain_snake_kernel(const float* __restrict__ x,
                                   const float* __restrict__ mu, const float* __restrict__ rs,
                                   const float* __restrict__ gb,
                                   const float* __restrict__ alpha,
                                   const float* __restrict__ inva,
                                   __half* __restrict__ outh)
{
    size_t idx = (size_t)blockIdx.x * blockDim.x + threadIdx.x;   // float4 index
    size_t e = idx * 4;
    int c = (int)(e & (Cc - 1));
    int b = (int)(e >> 21);

    float4 xv = ((const float4*)x)[idx];
    float4 gv = *(const float4*)(gb + (size_t)b * 2 * Cc + c);
    float4 bv = *(const float4*)(gb + (size_t)b * 2 * Cc + Cc + c);
    float4 mv = *(const float4*)(mu + b * Cc + c);
    float4 rv = *(const float4*)(rs + b * Cc + c);
    float4 av = *(const float4*)(alpha + c);
    float4 iv = *(const float4*)(inva + c);

    float o[4];
    {
        float xn = (xv.x - mv.x) * rv.x;
        float v  = (1.0f + gv.x) * xn + bv.x;
        float sn = __sinf(av.x * v);
        o[0] = v + sn * sn * iv.x;
    }
    {
        float xn = (xv.y - mv.y) * rv.y;
        float v  = (1.0f + gv.y) * xn + bv.y;
        float sn = __sinf(av.y * v);
        o[1] = v + sn * sn * iv.y;
    }
    {
        float xn = (xv.z - mv.z) * rv.z;
        float v  = (1.0f + gv.z) * xn + bv.z;
        float sn = __sinf(av.z * v);
        o[2] = v + sn * sn * iv.z;
    }
    {
        float xn = (xv.w - mv.w) * rv.w;
        float v  = (1.0f + gv.w) * xn + bv.w;
        float sn = __sinf(av.w * v);
        o[3] = v + sn * sn * iv.w;
    }

    uint32_t p0 = (uint32_t)__half_as_ushort(__float2half_rn(o[0])) |
                  ((uint32_t)__half_as_ushort(__float2half_rn(o[1])) << 16);
    uint32_t p1 = (uint32_t)__half_as_ushort(__float2half_rn(o[2])) |
                  ((uint32_t)__half_as_ushort(__float2half_rn(o[3])) << 16);
    ((uint2*)outh)[idx] = make_uint2(p0, p1);
}

// ---------------- dilated conv: mma.sync fp16 GEMM ------------------------------
__device__ __forceinline__ void load_stage(uint32_t sdst,
    const __half* __restrict__ A, const __half* __restrict__ W,
    int bb, int t0, int tap, int kk, int dil, int block_n, int tid)
{
#pragma unroll
    for (int q = 0; q < 4; q++) {
        int c   = tid + 256 * q;
        int row = c >> 3, k8 = c & 7;
        int tp  = t0 + row + (tap - 1) * dil;
        bool valid = ((unsigned)tp < (unsigned)Tt);
        size_t off = (((size_t)bb << 12) + (size_t)(valid ? tp : 0)) * Cc + kk + k8 * 8;
        uint32_t dst = sdst + row * (PITCH * 2) + k8 * 16;
        cp16z(dst, A + off, valid ? 16u : 0u);
    }
#pragma unroll
    for (int q = 0; q < 4; q++) {
        int c   = tid + 256 * q;
        int row = c >> 3, k8 = c & 7;
        size_t off = ((size_t)(tap * Cc + block_n + row)) * Cc + kk + k8 * 8;
        cp16(sdst + TILE_BYTES + row * (PITCH * 2) + k8 * 16, W + off);
    }
}

__global__ void __launch_bounds__(256, 2)
conv_mma_kernel(const __half* __restrict__ A, const __half* __restrict__ W,
                const float* __restrict__ bias, const float* __restrict__ res,
                float* __restrict__ out, float* __restrict__ statsPart, int dil)
{
    extern __shared__ __align__(16) char dsm[];
    const uint32_t sbase = smem_u32(dsm);

    const int tid  = threadIdx.x;
    const int wid  = tid >> 5;
    const int lane = tid & 31;

    const int block_m = blockIdx.x * 128;
    const int block_n = blockIdx.y * 128;
    const int bb = block_m >> 12;
    const int t0 = block_m & (Tt - 1);

    const int wm = (wid >> 2) * 64;   // warp m offset (0 or 64)
    const int wn = (wid & 3) * 32;    // warp n offset (0..96)

    float acc[4][4][4];
#pragma unroll
    for (int i = 0; i < 4; i++)
#pragma unroll
        for (int j = 0; j < 4; j++)
#pragma unroll
            for (int r = 0; r < 4; r++) acc[i][j][r] = 0.f;

    // prologue: stage 0 into buffer 0
    load_stage(sbase, A, W, bb, t0, 0, 0, dil, block_n, tid);
    CP_COMMIT();

    for (int s = 0; s < NSTAGES; ++s) {
        const uint32_t sbuf = sbase + (uint32_t)(s & 1) * STAGE_BYTES;
        if (s + 1 < NSTAGES) {
            const int tap = (s + 1) >> 3;
            const int kk  = ((s + 1) & 7) << 6;
            load_stage(sbase + (uint32_t)((s + 1) & 1) * STAGE_BYTES,
                       A, W, bb, t0, tap, kk, dil, block_n, tid);
            CP_COMMIT();
            CP_WAIT1();
        } else {
            CP_WAIT0();
        }
        __syncthreads();

        const uint32_t sA = sbuf;
        const uint32_t sW = sbuf + TILE_BYTES;

        // ldmatrix lane addressing (all non-trans)
        const int arow = lane & 15;
        const int ahalf = (lane >> 4) * 8;
        const int bn = (lane & 7) + ((lane >> 4) & 1) * 8;
        const int bk = ((lane >> 3) & 1) * 8;

#pragma unroll
        for (int ks = 0; ks < 4; ++ks) {
            const int kc = ks * 16;
            uint32_t ah[4][4], bh[2][4];
#pragma unroll
            for (int i = 0; i < 4; i++) {
                uint32_t aaddr = (uint32_t)((wm + i * 16 + arow) * (PITCH * 2) + (kc + ahalf) * 2);
                ldsm4(ah[i], sA + aaddr);
            }
#pragma unroll
            for (int j2 = 0; j2 < 2; j2++) {
                uint32_t baddr = (uint32_t)((wn + j2 * 16 + bn) * (PITCH * 2) + (kc + bk) * 2);
                ldsm4(bh[j2], sW + baddr);
            }
#pragma unroll
            for (int i = 0; i < 4; i++)
#pragma unroll
                for (int j = 0; j < 4; j++)
                    mma16816(acc[i][j], ah[i], &bh[j >> 1][(j & 1) * 2]);
        }
        __syncthreads();
    }

    // epilogue: bias (+ residual) + optional per-column stats partials
    float cs[4][2], cq[4][2];
#pragma unroll
    for (int j = 0; j < 4; j++) { cs[j][0] = cs[j][1] = cq[j][0] = cq[j][1] = 0.f; }

#pragma unroll
    for (int i = 0; i < 4; i++) {
#pragma unroll
        for (int j = 0; j < 4; j++) {
            const int col  = block_n + wn + j * 8 + (lane & 3) * 2;
            const int row0 = block_m + wm + i * 16 + (lane >> 2);
            const int row1 = row0 + 8;
            const float b0 = bias[col], b1 = bias[col + 1];

            float2 v0 = make_float2(acc[i][j][0] + b0, acc[i][j][1] + b1);
            float2 v1 = make_float2(acc[i][j][2] + b0, acc[i][j][3] + b1);
            if (res) {
                float2 r0 = *(const float2*)(res + (size_t)row0 * Cc + col);
                float2 r1 = *(const float2*)(res + (size_t)row1 * Cc + col);
                v0.x += r0.x; v0.y += r0.y;
                v1.x += r1.x; v1.y += r1.y;
            }
            *(float2*)(out + (size_t)row0 * Cc + col) = v0;
            *(float2*)(out + (size_t)row1 * Cc + col) = v1;

            cs[j][0] += v0.x + v1.x;
            cs[j][1] += v0.y + v1.y;
            cq[j][0] += v0.x * v0.x + v1.x * v1.x;
            cq[j][1] += v0.y * v0.y + v1.y * v1.y;
        }
    }

    if (statsPart) {
#pragma unroll
        for (int j = 0; j < 4; j++)
#pragma unroll
            for (int k = 0; k < 2; k++) {
#pragma unroll
                for (int off = 4; off < 32; off <<= 1) {
                    cs[j][k] += __shfl_xor_sync(0xffffffffu, cs[j][k], off);
                    cq[j][k] += __shfl_xor_sync(0xffffffffu, cq[j][k], off);
                }
            }
        float* ssum = (float*)dsm;          // [8][32]
        float* ssq  = ssum + 256;
        if (lane < 4) {
#pragma unroll
            for (int j = 0; j < 4; j++)
#pragma unroll
                for (int k = 0; k < 2; k++) {
                    int cc = j * 8 + lane * 2 + k;
                    ssum[wid * 32 + cc] = cs[j][k];
                    ssq [wid * 32 + cc] = cq[j][k];
                }
        }
        __syncthreads();
        const int si = (block_m >> 7) & 31;
        if (tid < 128) {
            int w = tid >> 5, cw = tid & 31;
            statsPart[((size_t)si * Bb + bb) * Cc + block_n + tid] =
                ssum[w * 32 + cw] + ssum[(w + 4) * 32 + cw];
        } else {
            int t2 = tid - 128;
            int w = t2 >> 5, cw = t2 & 31;
            statsPart[((size_t)(32 + si) * Bb + bb) * Cc + block_n + t2] =
                ssq[w * 32 + cw] + ssq[(w + 4) * 32 + cw];
        }
    }
}

// -------------------------------- launch --------------------------------------
extern "C" void kernel_launch(void* const* d_in, const int* in_sizes, int n_in,
                              void* d_out, int out_size)
{
    (void)in_sizes; (void)n_in; (void)out_size;
    const float* x      = (const float*)d_in[0];
    const float* s      = (const float*)d_in[1];
    const float* fc1w   = (const float*)d_in[2];
    const float* fc1b   = (const float*)d_in[3];
    const float* alpha1 = (const float*)d_in[4];
    const float* c1v    = (const float*)d_in[5];
    const float* c1g    = (const float*)d_in[6];
    const float* c1b    = (const float*)d_in[7];
    const float* fc2w   = (const float*)d_in[8];
    const float* fc2b   = (const float*)d_in[9];
    const float* alpha2 = (const float*)d_in[10];
    const float* c2v    = (const float*)d_in[11];
    const float* c2g    = (const float*)d_in[12];
    const float* c2b    = (const float*)d_in[13];
    float* out = (float*)d_out;

    __half *A, *W;
    float *T2, *X1, *SC, *GB, *MU, *RS, *PS, *IA;
    cudaGetSymbolAddress((void**)&A,   g_A);
    cudaGetSymbolAddress((void**)&T2,  g_T2);
    cudaGetSymbolAddress((void**)&X1,  g_X1);
    cudaGetSymbolAddress((void**)&W,   g_W);
    cudaGetSymbolAddress((void**)&SC,  g_SC);
    cudaGetSymbolAddress((void**)&GB,  g_GB);
    cudaGetSymbolAddress((void**)&MU,  g_MU);
    cudaGetSymbolAddress((void**)&RS,  g_RS);
    cudaGetSymbolAddress((void**)&PS,  g_PS);
    cudaGetSymbolAddress((void**)&IA,  g_IA);

    cudaFuncSetAttribute(conv_mma_kernel,
                         cudaFuncAttributeMaxDynamicSharedMemorySize, CONV_SMEM);

    // setup: style affines, weight-norm scale + inv-alpha, weight transpose
    style_kernel<<<6 * Bb, 256>>>(s, fc1w, fc1b, fc2w, fc2b, GB);
    wscale_kernel<<<6, Cc>>>(c1v, c1g, c2v, c2g, alpha1, alpha2, SC, IA);
    wtrans_kernel<<<dim3(16, 16, 18), dim3(32, 8)>>>(c1v, c2v, SC, W);

    const int dils[3] = {1, 3, 5};
    const size_t N4 = (size_t)Bb * Tt * Cc / 4;
    const int ew_blocks = (int)(N4 / 256);
    dim3 conv_grid((Bb * Tt) / 128, Cc / 128);
    const size_t KCC = (size_t)Kt * Cc * Cc;

    // initial stats on x
    initstats_kernel<<<dim3(32, Bb), 512>>>(x, PS);
    finalize_kernel<<<8, 512>>>(PS, MU, RS);

    for (int i = 0; i < 3; i++) {
        const float* xin  = (i == 0) ? x : X1;
        float*       xout = (i == 2) ? out : X1;

        adain_snake_kernel<<<ew_blocks, 256>>>(xin, MU, RS,
                                               GB + (size_t)(2 * i) * Bb * 2 * Cc,
                                               alpha1 + (size_t)i * Cc,
                                               IA + (size_t)(2 * i) * Cc, A);
        conv_mma_kernel<<<conv_grid, 256, CONV_SMEM>>>(A,
                                                       W + (size_t)(2 * i) * KCC,
                                                       c1b + (size_t)i * Cc, (const float*)0,
                                                       T2, PS, dils[i]);
        finalize_kernel<<<8, 512>>>(PS, MU, RS);
        adain_snake_kernel<<<ew_blocks, 256>>>(T2, MU, RS,
                                               GB + (size_t)(2 * i + 1) * Bb * 2 * Cc,
                                               alpha2 + (size_t)i * Cc,
                                               IA + (size_t)(2 * i + 1) * Cc, A);
        conv_mma_kernel<<<conv_grid, 256, CONV_SMEM>>>(A,
                                                       W + (size_t)(2 * i + 1) * KCC,
                                                       c2b + (size_t)i * Cc, xin,
                                                       xout, (i < 2) ? PS : (float*)0, 1);
        if (i < 2) finalize_kernel<<<8, 512>>>(PS, MU, RS);
    }
}

// round 8
// speedup vs baseline: 7.1027x; 1.0194x over previous
#include <cuda_runtime.h>
#include <cuda_fp16.h>
#include <math.h>
#include <stdint.h>

// Problem constants
#define Bb 8
#define Tt 4096
#define Cc 512
#define Kt 3
#define Ss 64

// Conv GEMM tiling
#define PITCH 72                         // fp16 elems per smem row (64 data + 8 pad)
#define TILE_BYTES (128 * PITCH * 2)     // 18432 B: one 128x64 fp16 tile
#define STAGE_BYTES (2 * TILE_BYTES)     // A, W
#define CONV_SMEM (2 * STAGE_BYTES)      // double buffered: 73728 B
#define NSTAGES 24                       // 3 taps x (512/64)

// ---------------- scratch (device globals; no runtime allocation) -------------
__device__ __half g_A [(size_t)Bb * Tt * Cc];             // fp16 activations
__device__ __half g_T2h[(size_t)Bb * Tt * Cc];            // fp16 conv1 output
__device__ float g_X1[(size_t)Bb * Tt * Cc];
__device__ __half g_W [(size_t)6 * Kt * Cc * Cc];         // [j][tap][cout][cin]
__device__ float g_SC[6 * Cc];
__device__ float g_GB[(size_t)6 * Bb * 2 * Cc];
__device__ float g_MU[Bb * Cc];
__device__ float g_RS[Bb * Cc];
__device__ float g_PS[2 * 64 * Bb * Cc];                  // per-slot partial sums/sumsq
__device__ float g_IA[6 * Cc];                            // 1/alpha per (block,layer)

// ================= PTX helpers (portable sm_80+ subset) ========================
__device__ __forceinline__ uint32_t smem_u32(const void* p) {
    uint32_t a;
    asm("{ .reg .u64 t; cvta.to.shared.u64 t, %1; cvt.u32.u64 %0, t; }" : "=r"(a) : "l"(p));
    return a;
}

__device__ __forceinline__ void mma16816(float* d, const uint32_t* a, const uint32_t* b) {
    asm volatile(
        "mma.sync.aligned.m16n8k16.row.col.f32.f16.f16.f32 "
        "{%0,%1,%2,%3}, {%4,%5,%6,%7}, {%8,%9}, {%0,%1,%2,%3};"
        : "+f"(d[0]), "+f"(d[1]), "+f"(d[2]), "+f"(d[3])
        : "r"(a[0]), "r"(a[1]), "r"(a[2]), "r"(a[3]), "r"(b[0]), "r"(b[1]));
}

__device__ __forceinline__ void ldsm4(uint32_t* r, uint32_t addr) {
    asm volatile("ldmatrix.sync.aligned.m8n8.x4.shared.b16 {%0,%1,%2,%3}, [%4];"
                 : "=r"(r[0]), "=r"(r[1]), "=r"(r[2]), "=r"(r[3]) : "r"(addr));
}

__device__ __forceinline__ void cp16(uint32_t dst, const void* src) {
    asm volatile("cp.async.cg.shared.global [%0], [%1], 16;" :: "r"(dst), "l"(src));
}
__device__ __forceinline__ void cp16z(uint32_t dst, const void* src, uint32_t n) {
    asm volatile("cp.async.cg.shared.global [%0], [%1], 16, %2;" :: "r"(dst), "l"(src), "r"(n));
}
#define CP_COMMIT() asm volatile("cp.async.commit_group;" ::: "memory")
#define CP_WAIT1()  asm volatile("cp.async.wait_group 1;" ::: "memory")
#define CP_WAIT0()  asm volatile("cp.async.wait_group 0;" ::: "memory")

// ---------------- style MLP ----------------------------------------------------
__global__ void style_kernel(const float* __restrict__ s,
                             const float* __restrict__ fc1w, const float* __restrict__ fc1b,
                             const float* __restrict__ fc2w, const float* __restrict__ fc2b,
                             float* __restrict__ gb)
{
    int j = blockIdx.x / Bb;
    int b = blockIdx.x % Bb;
    int i = j >> 1, layer = j & 1;
    const float* w  = (layer ? fc2w : fc1w) + (size_t)i * Ss * 2 * Cc;
    const float* bi = (layer ? fc2b : fc1b) + (size_t)i * 2 * Cc;

    __shared__ float ss[Ss];
    if (threadIdx.x < Ss) ss[threadIdx.x] = s[b * Ss + threadIdx.x];
    __syncthreads();

    for (int n = threadIdx.x; n < 2 * Cc; n += blockDim.x) {
        float acc = bi[n];
#pragma unroll 8
        for (int k = 0; k < Ss; k++) acc += ss[k] * w[(size_t)k * 2 * Cc + n];
        gb[((size_t)j * Bb + b) * 2 * Cc + n] = acc;
    }
}

// ---------------- weight norm scale + 1/alpha -----------------------------------
__global__ void wscale_kernel(const float* __restrict__ c1v, const float* __restrict__ c1g,
                              const float* __restrict__ c2v, const float* __restrict__ c2g,
                              const float* __restrict__ alpha1, const float* __restrict__ alpha2,
                              float* __restrict__ sc, float* __restrict__ ia)
{
    int j = blockIdx.x, co = threadIdx.x;
    int i = j >> 1, layer = j & 1;
    const float* v = (layer ? c2v : c1v) + (size_t)i * Kt * Cc * Cc;
    const float* g = (layer ? c2g : c1g) + (size_t)i * Cc;
    float s = 0.f;
    for (int r = 0; r < Kt * Cc; r++) {
        float t = v[(size_t)r * Cc + co];
        s += t * t;
    }
    sc[j * Cc + co] = g[co] * rsqrtf(s);
    const float* a = (layer ? alpha2 : alpha1) + (size_t)i * Cc;
    ia[j * Cc + co] = 1.0f / a[co];
}

// ---------------- transpose weights to [j][tap][cout][cin] fp16 ----------------
__global__ void wtrans_kernel(const float* __restrict__ c1v, const float* __restrict__ c2v,
                              const float* __restrict__ sc, __half* __restrict__ wout)
{
    int bz = blockIdx.z;
    int j = bz / 3, tap = bz % 3;
    int i = j >> 1, layer = j & 1;
    const float* v = (layer ? c2v : c1v) + (((size_t)i * Kt + tap) * Cc) * Cc;
    int ci0 = blockIdx.x * 32, co0 = blockIdx.y * 32;

    __shared__ float tile[32][33];
#pragma unroll
    for (int q = 0; q < 4; q++) {
        int ci = ci0 + threadIdx.y + q * 8;
        int co = co0 + threadIdx.x;
        tile[threadIdx.y + q * 8][threadIdx.x] = v[(size_t)ci * Cc + co] * sc[j * Cc + co];
    }
    __syncthreads();
    size_t wb = ((size_t)(j * Kt + tap)) * Cc * Cc;
#pragma unroll
    for (int q = 0; q < 4; q++) {
        int co = co0 + threadIdx.y + q * 8;
        int ci = ci0 + threadIdx.x;
        wout[wb + (size_t)co * Cc + ci] = __float2half_rn(tile[threadIdx.x][threadIdx.y + q * 8]);
    }
}

// ---------------- initial stats partials on x (64 slots, dual chains) ----------
__global__ void initstats_kernel(const float* __restrict__ x, float* __restrict__ ps)
{
    int si = blockIdx.x;           // 0..63 time slot (64 rows each)
    int b  = blockIdx.y;
    int c  = threadIdx.x;          // 0..511
    const float* p = x + (((size_t)b * Tt) + si * 64) * Cc + c;
    float S0 = 0.f, Q0 = 0.f, S1 = 0.f, Q1 = 0.f;
#pragma unroll 8
    for (int t = 0; t < 64; t += 2) {
        float v0 = p[(size_t)t * Cc];
        float v1 = p[(size_t)(t + 1) * Cc];
        S0 += v0; Q0 += v0 * v0;
        S1 += v1; Q1 += v1 * v1;
    }
    ps[((size_t)si * Bb + b) * Cc + c]        = S0 + S1;
    ps[((size_t)(64 + si) * Bb + b) * Cc + c] = Q0 + Q1;
}

// ---------------- finalize: partials -> mu, rsqrt(var+eps) ---------------------
__global__ void finalize_kernel(const float* __restrict__ ps,
                                float* __restrict__ mu, float* __restrict__ rs, int nslots)
{
    int idx = blockIdx.x * blockDim.x + threadIdx.x;   // 0..4095
    int b = idx >> 9, c = idx & 511;
    float S = 0.f, S2 = 0.f;
    for (int si = 0; si < nslots; si++) {
        S  += ps[((size_t)si * Bb + b) * Cc + c];
        S2 += ps[((size_t)(nslots + si) * Bb + b) * Cc + c];
    }
    float m   = S * (1.0f / Tt);
    float var = S2 * (1.0f / Tt) - m * m;
    mu[idx] = m;
    rs[idx] = rsqrtf(var + 1e-5f);
}

// ---------------- adain + snake, emitting fp16 ---------------------------------
template <bool IN_HALF>
__global__ void adain_snake_kernel(const void* __restrict__ xin,
                                   const float* __restrict__ mu, const float* __restrict__ rs,
                                   const float* __restrict__ gb,
                                   const float* __restrict__ alpha,
                                   const float* __restrict__ inva,
                                   __half* __restrict__ outh)
{
    const size_t base = (size_t)blockIdx.x * 512 + threadIdx.x;   // float4 index, 2 per thread
#pragma unroll
    for (int q = 0; q < 2; q++) {
        size_t idx = base + q * 256;
        size_t e = idx * 4;
        int c = (int)(e & (Cc - 1));
        int b = (int)(e >> 21);

        float xv[4];
        if (IN_HALF) {
            uint2 raw = ((const uint2*)xin)[idx];
            __half2 h0 = *(__half2*)&raw.x;
            __half2 h1 = *(__half2*)&raw.y;
            float2 f0 = __half22float2(h0), f1 = __half22float2(h1);
            xv[0] = f0.x; xv[1] = f0.y; xv[2] = f1.x; xv[3] = f1.y;
        } else {
            float4 f = ((const float4*)xin)[idx];
            xv[0] = f.x; xv[1] = f.y; xv[2] = f.z; xv[3] = f.w;
        }

        float4 gv = *(const float4*)(gb + (size_t)b * 2 * Cc + c);
        float4 bv = *(const float4*)(gb + (size_t)b * 2 * Cc + Cc + c);
        float4 mv = *(const float4*)(mu + b * Cc + c);
        float4 rv = *(const float4*)(rs + b * Cc + c);
        float4 av = *(const float4*)(alpha + c);
        float4 iv = *(const float4*)(inva + c);

        float o[4];
        {
            float v = (1.0f + gv.x) * ((xv[0] - mv.x) * rv.x) + bv.x;
            float sn = __sinf(av.x * v);
            o[0] = v + sn * sn * iv.x;
        }
        {
            float v = (1.0f + gv.y) * ((xv[1] - mv.y) * rv.y) + bv.y;
            float sn = __sinf(av.y * v);
            o[1] = v + sn * sn * iv.y;
        }
        {
            float v = (1.0f + gv.z) * ((xv[2] - mv.z) * rv.z) + bv.z;
            float sn = __sinf(av.z * v);
            o[2] = v + sn * sn * iv.z;
        }
        {
            float v = (1.0f + gv.w) * ((xv[3] - mv.w) * rv.w) + bv.w;
            float sn = __sinf(av.w * v);
            o[3] = v + sn * sn * iv.w;
        }

        uint32_t p0 = (uint32_t)__half_as_ushort(__float2half_rn(o[0])) |
                      ((uint32_t)__half_as_ushort(__float2half_rn(o[1])) << 16);
        uint32_t p1 = (uint32_t)__half_as_ushort(__float2half_rn(o[2])) |
                      ((uint32_t)__half_as_ushort(__float2half_rn(o[3])) << 16);
        ((uint2*)outh)[idx] = make_uint2(p0, p1);
    }
}

// ---------------- dilated conv: mma.sync fp16 GEMM ------------------------------
__device__ __forceinline__ void load_stage(uint32_t sdst,
    const __half* __restrict__ A, const __half* __restrict__ W,
    int bb, int t0, int tap, int kk, int dil, int block_n, int tid)
{
#pragma unroll
    for (int q = 0; q < 4; q++) {
        int c   = tid + 256 * q;
        int row = c >> 3, k8 = c & 7;
        int tp  = t0 + row + (tap - 1) * dil;
        bool valid = ((unsigned)tp < (unsigned)Tt);
        size_t off = (((size_t)bb << 12) + (size_t)(valid ? tp : 0)) * Cc + kk + k8 * 8;
        uint32_t dst = sdst + row * (PITCH * 2) + k8 * 16;
        cp16z(dst, A + off, valid ? 16u : 0u);
    }
#pragma unroll
    for (int q = 0; q < 4; q++) {
        int c   = tid + 256 * q;
        int row = c >> 3, k8 = c & 7;
        size_t off = ((size_t)(tap * Cc + block_n + row)) * Cc + kk + k8 * 8;
        cp16(sdst + TILE_BYTES + row * (PITCH * 2) + k8 * 16, W + off);
    }
}

template <bool OUT_HALF>
__global__ void __launch_bounds__(256, 2)
conv_mma_kernel(const __half* __restrict__ A, const __half* __restrict__ W,
                const float* __restrict__ bias, const float* __restrict__ res,
                void* __restrict__ out, float* __restrict__ statsPart, int dil)
{
    extern __shared__ __align__(16) char dsm[];
    const uint32_t sbase = smem_u32(dsm);

    const int tid  = threadIdx.x;
    const int wid  = tid >> 5;
    const int lane = tid & 31;

    const int block_m = blockIdx.x * 128;
    const int block_n = blockIdx.y * 128;
    const int bb = block_m >> 12;
    const int t0 = block_m & (Tt - 1);

    const int wm = (wid >> 2) * 64;   // warp m offset (0 or 64)
    const int wn = (wid & 3) * 32;    // warp n offset (0..96)

    float acc[4][4][4];
#pragma unroll
    for (int i = 0; i < 4; i++)
#pragma unroll
        for (int j = 0; j < 4; j++)
#pragma unroll
            for (int r = 0; r < 4; r++) acc[i][j][r] = 0.f;

    // prologue: stage 0 into buffer 0
    load_stage(sbase, A, W, bb, t0, 0, 0, dil, block_n, tid);
    CP_COMMIT();

    for (int s = 0; s < NSTAGES; ++s) {
        const uint32_t sbuf = sbase + (uint32_t)(s & 1) * STAGE_BYTES;
        if (s + 1 < NSTAGES) {
            const int tap = (s + 1) >> 3;
            const int kk  = ((s + 1) & 7) << 6;
            load_stage(sbase + (uint32_t)((s + 1) & 1) * STAGE_BYTES,
                       A, W, bb, t0, tap, kk, dil, block_n, tid);
            CP_COMMIT();
            CP_WAIT1();
        } else {
            CP_WAIT0();
        }
        __syncthreads();

        const uint32_t sA = sbuf;
        const uint32_t sW = sbuf + TILE_BYTES;

        // ldmatrix lane addressing (all non-trans)
        const int arow = lane & 15;
        const int ahalf = (lane >> 4) * 8;
        const int bn = (lane & 7) + ((lane >> 4) & 1) * 8;
        const int bk = ((lane >> 3) & 1) * 8;

#pragma unroll
        for (int ks = 0; ks < 4; ++ks) {
            const int kc = ks * 16;
            uint32_t ah[4][4], bh[2][4];
#pragma unroll
            for (int i = 0; i < 4; i++) {
                uint32_t aaddr = (uint32_t)((wm + i * 16 + arow) * (PITCH * 2) + (kc + ahalf) * 2);
                ldsm4(ah[i], sA + aaddr);
            }
#pragma unroll
            for (int j2 = 0; j2 < 2; j2++) {
                uint32_t baddr = (uint32_t)((wn + j2 * 16 + bn) * (PITCH * 2) + (kc + bk) * 2);
                ldsm4(bh[j2], sW + baddr);
            }
#pragma unroll
            for (int i = 0; i < 4; i++)
#pragma unroll
                for (int j = 0; j < 4; j++)
                    mma16816(acc[i][j], ah[i], &bh[j >> 1][(j & 1) * 2]);
        }
        __syncthreads();
    }

    // epilogue: bias (+ residual) + optional per-column stats partials
    float cs[4][2], cq[4][2];
#pragma unroll
    for (int j = 0; j < 4; j++) { cs[j][0] = cs[j][1] = cq[j][0] = cq[j][1] = 0.f; }

#pragma unroll
    for (int i = 0; i < 4; i++) {
#pragma unroll
        for (int j = 0; j < 4; j++) {
            const int col  = block_n + wn + j * 8 + (lane & 3) * 2;
            const int row0 = block_m + wm + i * 16 + (lane >> 2);
            const int row1 = row0 + 8;
            const float b0 = bias[col], b1 = bias[col + 1];

            float2 v0 = make_float2(acc[i][j][0] + b0, acc[i][j][1] + b1);
            float2 v1 = make_float2(acc[i][j][2] + b0, acc[i][j][3] + b1);
            if (res) {
                float2 r0 = *(const float2*)(res + (size_t)row0 * Cc + col);
                float2 r1 = *(const float2*)(res + (size_t)row1 * Cc + col);
                v0.x += r0.x; v0.y += r0.y;
                v1.x += r1.x; v1.y += r1.y;
            }
            if (OUT_HALF) {
                __half* oh = (__half*)out;
                __half2 h0 = __floats2half2_rn(v0.x, v0.y);
                __half2 h1 = __floats2half2_rn(v1.x, v1.y);
                *(__half2*)(oh + (size_t)row0 * Cc + col) = h0;
                *(__half2*)(oh + (size_t)row1 * Cc + col) = h1;
            } else {
                float* of = (float*)out;
                *(float2*)(of + (size_t)row0 * Cc + col) = v0;
                *(float2*)(of + (size_t)row1 * Cc + col) = v1;
            }

            cs[j][0] += v0.x + v1.x;
            cs[j][1] += v0.y + v1.y;
            cq[j][0] += v0.x * v0.x + v1.x * v1.x;
            cq[j][1] += v0.y * v0.y + v1.y * v1.y;
        }
    }

    if (statsPart) {
#pragma unroll
        for (int j = 0; j < 4; j++)
#pragma unroll
            for (int k = 0; k < 2; k++) {
#pragma unroll
                for (int off = 4; off < 32; off <<= 1) {
                    cs[j][k] += __shfl_xor_sync(0xffffffffu, cs[j][k], off);
                    cq[j][k] += __shfl_xor_sync(0xffffffffu, cq[j][k], off);
                }
            }
        float* ssum = (float*)dsm;          // [8][32]
        float* ssq  = ssum + 256;
        if (lane < 4) {
#pragma unroll
            for (int j = 0; j < 4; j++)
#pragma unroll
                for (int k = 0; k < 2; k++) {
                    int cc = j * 8 + lane * 2 + k;
                    ssum[wid * 32 + cc] = cs[j][k];
                    ssq [wid * 32 + cc] = cq[j][k];
                }
        }
        __syncthreads();
        const int si = (block_m >> 7) & 31;
        if (tid < 128) {
            int w = tid >> 5, cw = tid & 31;
            statsPart[((size_t)si * Bb + bb) * Cc + block_n + tid] =
                ssum[w * 32 + cw] + ssum[(w + 4) * 32 + cw];
        } else {
            int t2 = tid - 128;
            int w = t2 >> 5, cw = t2 & 31;
            statsPart[((size_t)(32 + si) * Bb + bb) * Cc + block_n + t2] =
                ssq[w * 32 + cw] + ssq[(w + 4) * 32 + cw];
        }
    }
}

// -------------------------------- launch --------------------------------------
extern "C" void kernel_launch(void* const* d_in, const int* in_sizes, int n_in,
                              void* d_out, int out_size)
{
    (void)in_sizes; (void)n_in; (void)out_size;
    const float* x      = (const float*)d_in[0];
    const float* s      = (const float*)d_in[1];
    const float* fc1w   = (const float*)d_in[2];
    const float* fc1b   = (const float*)d_in[3];
    const float* alpha1 = (const float*)d_in[4];
    const float* c1v    = (const float*)d_in[5];
    const float* c1g    = (const float*)d_in[6];
    const float* c1b    = (const float*)d_in[7];
    const float* fc2w   = (const float*)d_in[8];
    const float* fc2b   = (const float*)d_in[9];
    const float* alpha2 = (const float*)d_in[10];
    const float* c2v    = (const float*)d_in[11];
    const float* c2g    = (const float*)d_in[12];
    const float* c2b    = (const float*)d_in[13];
    float* out = (float*)d_out;

    __half *A, *T2h, *W;
    float *X1, *SC, *GB, *MU, *RS, *PS, *IA;
    cudaGetSymbolAddress((void**)&A,   g_A);
    cudaGetSymbolAddress((void**)&T2h, g_T2h);
    cudaGetSymbolAddress((void**)&X1,  g_X1);
    cudaGetSymbolAddress((void**)&W,   g_W);
    cudaGetSymbolAddress((void**)&SC,  g_SC);
    cudaGetSymbolAddress((void**)&GB,  g_GB);
    cudaGetSymbolAddress((void**)&MU,  g_MU);
    cudaGetSymbolAddress((void**)&RS,  g_RS);
    cudaGetSymbolAddress((void**)&PS,  g_PS);
    cudaGetSymbolAddress((void**)&IA,  g_IA);

    cudaFuncSetAttribute(conv_mma_kernel<true>,
                         cudaFuncAttributeMaxDynamicSharedMemorySize, CONV_SMEM);
    cudaFuncSetAttribute(conv_mma_kernel<false>,
                         cudaFuncAttributeMaxDynamicSharedMemorySize, CONV_SMEM);

    // setup: style affines, weight-norm scale + inv-alpha, weight transpose
    style_kernel<<<6 * Bb, 256>>>(s, fc1w, fc1b, fc2w, fc2b, GB);
    wscale_kernel<<<6, Cc>>>(c1v, c1g, c2v, c2g, alpha1, alpha2, SC, IA);
    wtrans_kernel<<<dim3(16, 16, 18), dim3(32, 8)>>>(c1v, c2v, SC, W);

    const int dils[3] = {1, 3, 5};
    const size_t N4 = (size_t)Bb * Tt * Cc / 4;
    const int ew_blocks = (int)(N4 / 512);          // 2 float4 per thread
    dim3 conv_grid((Bb * Tt) / 128, Cc / 128);
    const size_t KCC = (size_t)Kt * Cc * Cc;

    // initial stats on x
    initstats_kernel<<<dim3(64, Bb), 512>>>(x, PS);
    finalize_kernel<<<8, 512>>>(PS, MU, RS, 64);

    for (int i = 0; i < 3; i++) {
        const float* xin  = (i == 0) ? x : X1;
        float*       xout = (i == 2) ? out : X1;

        adain_snake_kernel<false><<<ew_blocks, 256>>>(xin, MU, RS,
                                                      GB + (size_t)(2 * i) * Bb * 2 * Cc,
                                                      alpha1 + (size_t)i * Cc,
                                                      IA + (size_t)(2 * i) * Cc, A);
        conv_mma_kernel<true><<<conv_grid, 256, CONV_SMEM>>>(A,
                                                      W + (size_t)(2 * i) * KCC,
                                                      c1b + (size_t)i * Cc, (const float*)0,
                                                      T2h, PS, dils[i]);
        finalize_kernel<<<8, 512>>>(PS, MU, RS, 32);
        adain_snake_kernel<true><<<ew_blocks, 256>>>(T2h, MU, RS,
                                                     GB + (size_t)(2 * i + 1) * Bb * 2 * Cc,
                                                     alpha2 + (size_t)i * Cc,
                                                     IA + (size_t)(2 * i + 1) * Cc, A);
        conv_mma_kernel<false><<<conv_grid, 256, CONV_SMEM>>>(A,
                                                      W + (size_t)(2 * i + 1) * KCC,
                                                      c2b + (size_t)i * Cc, xin,
                                                      xout, (i < 2) ? PS : (float*)0, 1);
        if (i < 2) finalize_kernel<<<8, 512>>>(PS, MU, RS, 32);
    }
}